// round 8
// baseline (speedup 1.0000x reference)
#include <cuda_runtime.h>

// ---------------- problem constants ----------------
constexpr int NB    = 8;
constexpr int NT    = 5;
constexpr int NL    = 16;
constexpr int NTEST = NB * NL;          // 128
constexpr int NCLS  = 100;
constexpr int FEAT  = 4096;
constexpr int CHW   = 3 * 64 * 64;

constexpr int OFF_W0 = 0;        constexpr int SZ_W0 = 32 * 3 * 9;
constexpr int OFF_B0 = 864;      constexpr int SZ_B0 = 32;
constexpr int OFF_W1 = 896;      constexpr int SZ_W1 = 64 * 32 * 9;
constexpr int OFF_B1 = 19328;    constexpr int SZ_B1 = 64;
constexpr int OFF_W2 = 19392;    constexpr int SZ_W2 = 128 * 64 * 9;
constexpr int OFF_B2 = 93120;    constexpr int SZ_B2 = 128;
constexpr int OFF_W3 = 93248;    constexpr int SZ_W3 = 256 * 128 * 9;
constexpr int OFF_B3 = 388160;   constexpr int SZ_B3 = 256;
constexpr int OFF_W4 = 388416;   constexpr int SZ_W4 = 256 * 256 * 9;
constexpr int OFF_B4 = 978240;   constexpr int SZ_B4 = 256;
constexpr int OFF_WO = 978496;   constexpr int SZ_WO = NCLS * FEAT;
constexpr int OFF_BO = 1388096;  constexpr int SZ_BO = NCLS;
constexpr int PTOT   = 1388196;

constexpr int GRIDN = 444;   // 3 blocks/SM on 148 SMs -> all resident (enforced by launch_bounds)

// ---------------- static device scratch ----------------
__device__ float g_fw  [NB * PTOT];
__device__ float g_a1[NB * 131072];
__device__ float g_a2[NB * 65536];
__device__ float g_a3[NB * 32768];
__device__ float g_a4[NB * 16384];
__device__ float g_a5[NB * 4096];
__device__ float g_feat[NB * FEAT];
__device__ float g_logit[NB * NCLS];
__device__ float g_dlogit[NB * NCLS];
__device__ float g_z1[NB * 131072];
__device__ float g_z2[NB * 131072];
__device__ float g_r1[NB * 131072];
__device__ float g_r2[NB * 131072];
__device__ float g_hr[NB * FEAT];
__device__ float g_ta[NTEST * 131072];
__device__ float g_tb[NTEST * 131072];
__device__ unsigned g_gen;
__device__ unsigned g_cnt;

// ---------------- software grid barrier ----------------
__device__ __forceinline__ void gsync()
{
    __syncthreads();
    if (threadIdx.x == 0) {
        __threadfence();
        unsigned gen = *((volatile unsigned*)&g_gen);
        unsigned my  = atomicAdd(&g_cnt, 1u);
        if (my == GRIDN - 1) {
            atomicExch(&g_cnt, 0u);
            __threadfence();
            atomicAdd(&g_gen, 1u);
        } else {
            while (*((volatile unsigned*)&g_gen) == gen) __nanosleep(128);
        }
        __threadfence();
    }
    __syncthreads();
}

// ---------------- device per-item helpers (inner loop) ----------------
// L0 direct conv: S=1, TOC=4, TOX=4, IC=3, OC=32, 64x64. Items: NB*8*64*16 = 65536
__device__ __forceinline__ void dev_fwd0(long idx, const float* __restrict__ in, long in_stride,
                                         const float* __restrict__ fw, float* __restrict__ out)
{
    int ox0 = (int)(idx % 16) * 4; long t = idx / 16;
    int oy  = (int)(t % 64);       t /= 64;
    int oc0 = (int)(t % 8) * 4;    int n = (int)(t / 8);
    const float* wbase = fw + (long)n * PTOT + OFF_W0;
    const float* x     = in + (long)n * in_stride;
    float acc[4][4];
#pragma unroll
    for (int i = 0; i < 4; i++) {
        float bv = fw[(long)n * PTOT + OFF_B0 + oc0 + i];
#pragma unroll
        for (int j = 0; j < 4; j++) acc[i][j] = bv;
    }
    int ixb = ox0 - 1;
#pragma unroll
    for (int ic = 0; ic < 3; ic++) {
        const float* xc = x + (long)ic * 4096;
#pragma unroll
        for (int ky = 0; ky < 3; ky++) {
            int iy = oy - 1 + ky;
            if ((unsigned)iy >= 64u) continue;
            const float* xr = xc + iy * 64;
            float xv[6];
#pragma unroll
            for (int u = 0; u < 6; u++) {
                int ix = ixb + u;
                xv[u] = ((unsigned)ix < 64u) ? xr[ix] : 0.f;
            }
#pragma unroll
            for (int i = 0; i < 4; i++) {
                const float* wp = wbase + ((long)(oc0 + i) * 3 + ic) * 9 + ky * 3;
                float w0 = wp[0], w1 = wp[1], w2 = wp[2];
#pragma unroll
                for (int j = 0; j < 4; j++)
                    acc[i][j] = fmaf(w0, xv[j], fmaf(w1, xv[j + 1], fmaf(w2, xv[j + 2], acc[i][j])));
            }
        }
    }
#pragma unroll
    for (int i = 0; i < 4; i++) {
        float* op = out + (((long)n * 32 + oc0 + i) * 64 + oy) * 64 + ox0;
#pragma unroll
        for (int j = 0; j < 4; j++) op[j] = fmaxf(acc[i][j], 0.f);
    }
}

// chunked conv fwd: S=2, TOC=4, TOX=4, atomic accumulate (no bias/relu)
__device__ __forceinline__ void dev_fwd_chunk(long idx, const float* __restrict__ in,
                                              const float* __restrict__ fw, int woff,
                                              float* __restrict__ out,
                                              int IC, int OC, int IH, int IW, int OH, int OW, int ICH)
{
    int nox = OW >> 2, noc = OC >> 2;
    long base = (long)NB * noc * OH * nox;
    int ch = (int)(idx / base); long r = idx % base;
    int ox0 = (int)(r % nox) * 4; long t = r / nox;
    int oy  = (int)(t % OH);      t /= OH;
    int oc0 = (int)(t % noc) * 4; int n = (int)(t / noc);
    const float* wbase = fw + (long)n * PTOT + woff;
    const float* x     = in + (long)n * IC * IH * IW;
    float acc[4][4];
#pragma unroll
    for (int i = 0; i < 4; i++)
#pragma unroll
        for (int j = 0; j < 4; j++) acc[i][j] = 0.f;
    int ixb = ox0 * 2 - 1;
    int ic0 = ch * ICH;
    for (int ic = ic0; ic < ic0 + ICH; ic++) {
        const float* xc = x + (long)ic * IH * IW;
#pragma unroll
        for (int ky = 0; ky < 3; ky++) {
            int iy = oy * 2 - 1 + ky;
            if ((unsigned)iy >= (unsigned)IH) continue;
            const float* xr = xc + iy * IW;
            float xv[9];
#pragma unroll
            for (int u = 0; u < 9; u++) {
                int ix = ixb + u;
                xv[u] = ((unsigned)ix < (unsigned)IW) ? xr[ix] : 0.f;
            }
#pragma unroll
            for (int i = 0; i < 4; i++) {
                const float* wp = wbase + ((long)(oc0 + i) * IC + ic) * 9 + ky * 3;
                float w0 = wp[0], w1 = wp[1], w2 = wp[2];
#pragma unroll
                for (int j = 0; j < 4; j++)
                    acc[i][j] = fmaf(w0, xv[j * 2],
                                fmaf(w1, xv[j * 2 + 1], fmaf(w2, xv[j * 2 + 2], acc[i][j])));
            }
        }
    }
#pragma unroll
    for (int i = 0; i < 4; i++) {
        float* op = out + (((long)n * OC + oc0 + i) * OH + oy) * OW + ox0;
#pragma unroll
        for (int j = 0; j < 4; j++) atomicAdd(op + j, acc[i][j]);
    }
}

// head dot: one warp per (n, cls, chunk-of-256); 16 chunks
__device__ __forceinline__ void dev_headdot(long w, const float* __restrict__ feat,
                                            const float* __restrict__ fw,
                                            float* __restrict__ logits, int lane)
{
    int ch = (int)(w & 15); long w2 = w >> 4;
    int cls = (int)(w2 % NCLS); int n = (int)(w2 / NCLS);
    const float* wt = fw + (long)n * PTOT + OFF_WO + (long)cls * FEAT + ch * 256;
    const float* f  = feat + (long)n * FEAT + ch * 256;
    float acc = 0.f;
#pragma unroll
    for (int m = lane; m < 256; m += 32) acc = fmaf(wt[m], f[m], acc);
#pragma unroll
    for (int o = 16; o; o >>= 1) acc += __shfl_down_sync(0xffffffffu, acc, o);
    if (!lane) atomicAdd(&logits[w2], acc);
}

// softmax-CE grad per example (one warp), fused b_out update
__device__ __forceinline__ void dev_ce(int b, const float* __restrict__ logits,
                                       const int* __restrict__ y, int t,
                                       float* __restrict__ dlogit, float* __restrict__ fw,
                                       float lr, int lane)
{
    float v[4]; float mx = -1e30f;
#pragma unroll
    for (int k = 0; k < 4; k++) {
        int c = lane + 32 * k;
        v[k] = (c < NCLS) ? logits[b * NCLS + c] : -1e30f;
        mx = fmaxf(mx, v[k]);
    }
#pragma unroll
    for (int o = 16; o; o >>= 1) mx = fmaxf(mx, __shfl_xor_sync(0xffffffffu, mx, o));
    float e[4]; float s = 0.f;
#pragma unroll
    for (int k = 0; k < 4; k++) {
        int c = lane + 32 * k;
        e[k] = (c < NCLS) ? expf(v[k] - mx) : 0.f;
        s += e[k];
    }
#pragma unroll
    for (int o = 16; o; o >>= 1) s += __shfl_xor_sync(0xffffffffu, s, o);
    int label = y[b * NT + t];
#pragma unroll
    for (int k = 0; k < 4; k++) {
        int c = lane + 32 * k;
        if (c < NCLS) {
            float dl = e[k] / s - (c == label ? 1.f : 0.f);
            dlogit[b * NCLS + c] = dl;
            fw[(long)b * PTOT + OFF_BO + c] -= lr * dl;
        }
    }
}

// head bwd to features: chunk of 10 classes (10 chunks), atomic into hr
__device__ __forceinline__ void dev_bwdf(long i, const float* __restrict__ dlogit,
                                         const float* __restrict__ fw, float* __restrict__ hr)
{
    int m = (int)(i % FEAT); long t2 = i / FEAT;
    int ch = (int)(t2 % 10); int b = (int)(t2 / 10);
    const float* w  = fw + (long)b * PTOT + OFF_WO + m + (long)(ch * 10) * FEAT;
    const float* dl = dlogit + b * NCLS + ch * 10;
    float acc = 0.f;
#pragma unroll
    for (int n = 0; n < 10; n++) acc = fmaf(w[(long)n * FEAT], dl[n], acc);
    atomicAdd(&hr[(long)b * FEAT + m], acc);
}

// bias grad + update: one warp per (b, oc)
__device__ __forceinline__ void dev_bwdb(long w, const float* __restrict__ dz,
                                         float* __restrict__ fw, float lr,
                                         int boff, int OC, int OHW, int lane)
{
    int oc = (int)(w % OC); int b = (int)(w / OC);
    const float* p = dz + ((long)b * OC + oc) * OHW;
    float acc = 0.f;
    for (int i = lane; i < OHW; i += 32) acc += p[i];
#pragma unroll
    for (int o = 16; o; o >>= 1) acc += __shfl_down_sync(0xffffffffu, acc, o);
    if (!lane) fw[(long)b * PTOT + boff + oc] -= lr * acc;
}

// WARP-COOPERATIVE weight grad + fused SGD.
// One warp per (b, oc, ic, oy-chunk); lanes sweep consecutive (oy,ox) pixels.
// z-loads coalesced, x-loads stride-S (<=2 lines/warp). 9 accs -> warp reduce -> 9 atomics.
__device__ __forceinline__ void dev_bwdw_warp(long w, const float* __restrict__ dz,
                                              const float* __restrict__ xin, long xin_stride,
                                              float* __restrict__ fw, float nlr, int woff,
                                              int IC, int OC, int IH, int IW, int OH, int OW,
                                              int NCH, int S, int lane)
{
    int c  = (int)(w % NCH); long t = w / NCH;
    int ic = (int)(t % IC); t /= IC;
    int oc = (int)(t % OC); int b = (int)(t / OC);
    int CH = OH / NCH;
    const float* x = xin + (long)b * xin_stride + (long)ic * IH * IW;
    const float* z = dz + ((long)b * OC + oc) * OH * OW;
    float acc[9];
#pragma unroll
    for (int k = 0; k < 9; k++) acc[k] = 0.f;
    int oybase = c * CH;
    int npix = CH * OW;
    for (int p = lane; p < npix; p += 32) {
        int oy = oybase + p / OW;
        int ox = p % OW;
        float zv = z[oy * OW + ox];
#pragma unroll
        for (int ky = 0; ky < 3; ky++) {
            int iy = oy * S + ky - 1;
            if ((unsigned)iy >= (unsigned)IH) continue;
            const float* xr = x + iy * IW;
            int ixb = ox * S - 1;
#pragma unroll
            for (int kx = 0; kx < 3; kx++) {
                int ix = ixb + kx;
                if ((unsigned)ix < (unsigned)IW)
                    acc[ky * 3 + kx] = fmaf(zv, xr[ix], acc[ky * 3 + kx]);
            }
        }
    }
    float* g = fw + (long)b * PTOT + woff + ((long)oc * IC + ic) * 9;
#pragma unroll
    for (int k = 0; k < 9; k++) {
        float v = acc[k];
#pragma unroll
        for (int o = 16; o; o >>= 1) v += __shfl_down_sync(0xffffffffu, v, o);
        if (!lane) atomicAdd(g + k, nlr * v);
    }
}

// dx chunked over OC (OCH per chunk), 4 consecutive pixels, atomic into raw
__device__ __forceinline__ void dev_bwdx(long idx, const float* __restrict__ dz,
                                         const float* __restrict__ fw, int woff,
                                         float* __restrict__ raw,
                                         int IC, int OC, int IH, int IW, int OH, int OW, int OCH)
{
    int nix = IW >> 2;
    long base = (long)NB * IC * IH * nix;
    int ch = (int)(idx / base); long r = idx % base;
    int ix0 = (int)(r % nix) * 4; long t = r / nix;
    int iy = (int)(t % IH); t /= IH;
    int ic = (int)(t % IC); int b = (int)(t / IC);
    long pix = (((long)b * IC + ic) * IH + iy) * IW + ix0;

    float acc0 = 0.f, acc1 = 0.f, acc2 = 0.f, acc3 = 0.f;
    int ox0p = ix0 >> 1;
    bool ok2 = (ox0p + 2 < OW), ok1 = (ox0p + 1 < OW);
    int oyv[3]; bool kyok[3];
#pragma unroll
    for (int ky = 0; ky < 3; ky++) {
        int ty = iy + 1 - ky;
        kyok[ky] = (ty >= 0) && !(ty & 1) && ((ty >> 1) < OH);
        oyv[ky] = ty >> 1;
    }
    const float* wb = fw + (long)b * PTOT + woff + (long)ic * 9;
    const float* zb = dz + (long)b * OC * OH * OW;
    int oc0 = ch * OCH;
    for (int oc = oc0; oc < oc0 + OCH; oc++) {
        const float* wp = wb + (long)oc * IC * 9;
        const float* zp = zb + (long)oc * OH * OW;
#pragma unroll
        for (int ky = 0; ky < 3; ky++) {
            if (!kyok[ky]) continue;
            const float* zr = zp + oyv[ky] * OW;
            float d0 = zr[ox0p];
            float d1 = ok1 ? zr[ox0p + 1] : 0.f;
            float d2 = ok2 ? zr[ox0p + 2] : 0.f;
            float wk0 = wp[ky * 3 + 0], wk1 = wp[ky * 3 + 1], wk2 = wp[ky * 3 + 2];
            acc0 = fmaf(wk1, d0, acc0);
            acc1 = fmaf(wk0, d1, fmaf(wk2, d0, acc1));
            acc2 = fmaf(wk1, d1, acc2);
            acc3 = fmaf(wk0, d2, fmaf(wk2, d1, acc3));
        }
    }
    atomicAdd(&raw[pix],     acc0);
    atomicAdd(&raw[pix + 1], acc1);
    atomicAdd(&raw[pix + 2], acc2);
    atomicAdd(&raw[pix + 3], acc3);
}

// ---------------- the inner-loop megakernel ----------------
__global__ __launch_bounds__(256, 3) void k_inner(
    const float* w0c, const float* b0c, const float* w1c, const float* b1c,
    const float* w2c, const float* b2c, const float* w3c, const float* b3c,
    const float* w4c, const float* b4c, const float* woc, const float* boc,
    const float* log_lr, const float* train_x, const float* train_gate, const int* train_y)
{
    float* fw = g_fw;
    const long tstep = (long)GRIDN * 256;
    const long tid0  = blockIdx.x * 256L + threadIdx.x;
    const int  lane  = threadIdx.x & 31;
    const long wid0  = blockIdx.x * 8L + (threadIdx.x >> 5);
    const long wstep = (long)GRIDN * 8;
    const float lr   = expf(*log_lr);

    // layer metadata
    const int LIC[5] = {3, 32, 64, 128, 256};
    const int LOC[5] = {32, 64, 128, 256, 256};
    const int LIH[5] = {64, 64, 32, 16, 8};
    const int LOH[5] = {64, 32, 16, 8, 4};
    const int LWO[5] = {OFF_W0, OFF_W1, OFF_W2, OFF_W3, OFF_W4};
    const int LBO[5] = {OFF_B0, OFF_B1, OFF_B2, OFF_B3, OFF_B4};
    const int LICH[5] = {0, 2, 2, 2, 1};       // fwd IC-chunks
    const int LWN[5]  = {16, 4, 2, 1, 1};      // bwd_w oy-chunks (warp-coop: rounds of <=8)
    const int LXCH[5] = {0, 32, 32, 32, 16};   // bwd_x OC chunk
    float* ACT[5] = {nullptr, g_a1, g_a2, g_a3, g_a4};   // input act of layer j
    long INSZ[5];
    for (int j = 0; j < 5; j++) INSZ[j] = (long)NB * LIC[j] * LIH[j] * LIH[j];

    // ---- broadcast params ----
    {
        const float* src[12] = {w0c, b0c, w1c, b1c, w2c, b2c, w3c, b3c, w4c, b4c, woc, boc};
        const int offs[12] = {OFF_W0, OFF_B0, OFF_W1, OFF_B1, OFF_W2, OFF_B2,
                              OFF_W3, OFF_B3, OFF_W4, OFF_B4, OFF_WO, OFF_BO};
        const int szs[12]  = {SZ_W0, SZ_B0, SZ_W1, SZ_B1, SZ_W2, SZ_B2,
                              SZ_W3, SZ_B3, SZ_W4, SZ_B4, SZ_WO, SZ_BO};
        for (int k = 0; k < 12; k++) {
            long n = (long)NB * szs[k];
            for (long i = tid0; i < n; i += tstep)
                fw[(i / szs[k]) * (long)PTOT + offs[k] + (i % szs[k])] = src[k][i % szs[k]];
        }
    }
    gsync();

    // forward chunked layer: accumulate phase (+optional zero of another buf), then bias+relu
    auto phase_fwd = [&](int j, const float* in, float* o, float* zbuf, long zcnt) {
        int IC = LIC[j], OC = LOC[j], IH = LIH[j], OH = LOH[j];
        long tot = (long)NB * (OC >> 2) * OH * (OH >> 2) * (IC / LICH[j]);
        for (long i = tid0; i < tot; i += tstep)
            dev_fwd_chunk(i, in, fw, LWO[j], o, IC, OC, IH, IH, OH, OH, LICH[j]);
        if (zbuf) for (long i = tid0; i < zcnt; i += tstep) zbuf[i] = 0.f;
        gsync();
        long osz = (long)NB * OC * OH * OH;
        int boff = LBO[j];
        for (long i = tid0; i < osz; i += tstep) {
            int oc = (int)((i / (OH * OH)) % OC);
            int n  = (int)(i / ((long)OC * OH * OH));
            o[i] = fmaxf(o[i] + fw[(long)n * PTOT + boff + oc], 0.f);
        }
        gsync();
    };

    for (int t = 0; t < NT; t++) {
        const float* in0  = train_x + (long)t * CHW;
        const float* gptr = train_gate + (long)t * FEAT;

        // P0: conv L0 (direct, fused bias+relu) + zero a2.  65536 = NB*8*64*16 items.
        for (long i = tid0; i < 65536; i += tstep) dev_fwd0(i, in0, (long)NT * CHW, fw, g_a1);
        for (long i = tid0; i < (long)NB * 65536; i += tstep) g_a2[i] = 0.f;
        gsync();
        phase_fwd(1, g_a1, g_a2, g_a3, (long)NB * 32768);
        phase_fwd(2, g_a2, g_a3, g_a4, (long)NB * 16384);
        phase_fwd(3, g_a3, g_a4, g_a5, (long)NB * 4096);
        phase_fwd(4, g_a4, g_a5, nullptr, 0);

        // gate + logit init + zero hr
        for (long i = tid0; i < (long)NB * FEAT; i += tstep) {
            int n = (int)(i / FEAT), m = (int)(i % FEAT);
            g_feat[i] = g_a5[i] * gptr[(long)n * NT * FEAT + m];
        }
        for (long i = tid0; i < (long)NB * NCLS; i += tstep)
            g_logit[i] = fw[(i / NCLS) * (long)PTOT + OFF_BO + (i % NCLS)];
        for (long i = tid0; i < (long)NB * FEAT; i += tstep) g_hr[i] = 0.f;
        gsync();

        // head dot (16 chunks of 256)
        for (long w = wid0; w < (long)NB * NCLS * 16; w += wstep)
            dev_headdot(w, g_feat, fw, g_logit, lane);
        gsync();

        // softmax-CE grad (+ b_out update)
        for (long w = wid0; w < NB; w += wstep)
            dev_ce((int)w, g_logit, train_y, t, g_dlogit, fw, lr, lane);
        gsync();

        // head bwd to features (raw, reads pre-update W_out); 10 chunks of 10 classes
        for (long i = tid0; i < (long)NB * 10 * FEAT; i += tstep)
            dev_bwdf(i, g_dlogit, fw, g_hr);
        gsync();

        // maskgate -> z1 ; W_out update ; zero r1 (layer-4 raw)
        for (long i = tid0; i < (long)NB * FEAT; i += tstep) {
            int n = (int)(i / FEAT), m = (int)(i % FEAT);
            g_z1[i] = (g_a5[i] > 0.f) ? g_hr[i] * gptr[(long)n * NT * FEAT + m] : 0.f;
        }
        for (long i = tid0; i < (long)NB * NCLS * FEAT; i += tstep) {
            int m = (int)(i % FEAT); long t2 = i / FEAT;
            int cls = (int)(t2 % NCLS); int b = (int)(t2 / NCLS);
            fw[(long)b * PTOT + OFF_WO + (long)cls * FEAT + m] -=
                lr * g_dlogit[b * NCLS + cls] * g_feat[(long)b * FEAT + m];
        }
        for (long i = tid0; i < INSZ[4]; i += tstep) g_r1[i] = 0.f;
        gsync();

        // backward conv layers
        float *zp = g_z1, *zq = g_z2, *rp = g_r1, *rq = g_r2;
        for (int j = 4; j >= 1; j--) {
            int IC = LIC[j], OC = LOC[j], IH = LIH[j], OH = LOH[j];
            // P_A: bias grad+upd ; dx accumulation (reads pre-update W_j)
            for (long w = wid0; w < (long)NB * OC; w += wstep)
                dev_bwdb(w, zp, fw, lr, LBO[j], OC, OH * OH, lane);
            long xtot = (long)NB * IC * IH * (IH >> 2) * (OC / LXCH[j]);
            for (long i = tid0; i < xtot; i += tstep)
                dev_bwdx(i, zp, fw, LWO[j], rp, IC, OC, IH, IH, OH, OH, LXCH[j]);
            gsync();
            // P_B: W_j grad+upd (warp-cooperative, coalesced) ; mask rp->zq ; zero rq
            long wtot = (long)NB * OC * IC * LWN[j];
            for (long w = wid0; w < wtot; w += wstep)
                dev_bwdw_warp(w, zp, ACT[j], (long)IC * IH * IH, fw, -lr, LWO[j],
                              IC, OC, IH, IH, OH, OH, LWN[j], 2, lane);
            const float* ain = ACT[j];
            for (long i = tid0; i < INSZ[j]; i += tstep)
                zq[i] = (ain[i] > 0.f) ? rp[i] : 0.f;
            if (j > 1)
                for (long i = tid0; i < INSZ[j - 1]; i += tstep) rq[i] = 0.f;
            gsync();
            float* tmp;
            tmp = zp; zp = zq; zq = tmp;
            tmp = rp; rp = rq; rq = tmp;
        }
        // L0: bias + weight update (no dx needed); warp-cooperative bwd_w, S=1
        for (long w = wid0; w < (long)NB * 32; w += wstep)
            dev_bwdb(w, zp, fw, lr, OFF_B0, 32, 4096, lane);
        for (long w = wid0; w < (long)NB * 32 * 3 * LWN[0]; w += wstep)
            dev_bwdw_warp(w, zp, in0, (long)NT * CHW, fw, -lr, OFF_W0,
                          3, 32, 64, 64, 64, 64, LWN[0], 1, lane);
        gsync();
    }
}

// ---------------- test-path kernels ----------------
template<int S, int TOC, int TOX>
__global__ void k_conv_fwd_t(const float* __restrict__ in, long in_stride,
                             const float* __restrict__ fw, int woff, int boff, int wdiv,
                             float* __restrict__ out,
                             int N, int IC, int OC, int IH, int IW, int OH, int OW)
{
    constexpr int XLEN = (TOX - 1) * S + 3;
    int idx = blockIdx.x * 256 + threadIdx.x;
    int nox = OW / TOX;
    int noc = OC / TOC;
    if (idx >= N * noc * OH * nox) return;
    int ox0 = (idx % nox) * TOX; int t = idx / nox;
    int oy  = t % OH;            t /= OH;
    int oc0 = (t % noc) * TOC;   int n = t / noc;
    long ex = n / wdiv;
    const float* wbase = fw + ex * PTOT + woff;
    const float* x     = in + (long)n * in_stride;

    float acc[TOC][TOX];
#pragma unroll
    for (int i = 0; i < TOC; i++) {
        float bv = fw[ex * PTOT + boff + oc0 + i];
#pragma unroll
        for (int j = 0; j < TOX; j++) acc[i][j] = bv;
    }
    int ixb = ox0 * S - 1;
    for (int ic = 0; ic < IC; ic++) {
        const float* xc = x + (long)ic * IH * IW;
#pragma unroll
        for (int ky = 0; ky < 3; ky++) {
            int iy = oy * S - 1 + ky;
            if ((unsigned)iy >= (unsigned)IH) continue;
            const float* xr = xc + iy * IW;
            float xv[XLEN];
#pragma unroll
            for (int u = 0; u < XLEN; u++) {
                int ix = ixb + u;
                xv[u] = ((unsigned)ix < (unsigned)IW) ? xr[ix] : 0.f;
            }
#pragma unroll
            for (int i = 0; i < TOC; i++) {
                const float* wp = wbase + ((long)(oc0 + i) * IC + ic) * 9 + ky * 3;
                float w0 = wp[0], w1 = wp[1], w2 = wp[2];
#pragma unroll
                for (int j = 0; j < TOX; j++)
                    acc[i][j] = fmaf(w0, xv[j * S],
                                fmaf(w1, xv[j * S + 1],
                                fmaf(w2, xv[j * S + 2], acc[i][j])));
            }
        }
    }
#pragma unroll
    for (int i = 0; i < TOC; i++) {
        float* op = out + (((long)n * OC + oc0 + i) * OH + oy) * OW + ox0;
#pragma unroll
        for (int j = 0; j < TOX; j++) op[j] = fmaxf(acc[i][j], 0.f);
    }
}

template<int S, int TOC, int TOX>
__global__ void k_conv_fwd_chunk(const float* __restrict__ in, long in_stride,
                                 const float* __restrict__ fw, int woff, int wdiv,
                                 float* __restrict__ out,
                                 int N, int IC, int OC, int IH, int IW, int OH, int OW,
                                 int NCHUNK, int ICH)
{
    constexpr int XLEN = (TOX - 1) * S + 3;
    int nox = OW / TOX;
    int noc = OC / TOC;
    int base = N * noc * OH * nox;
    int idx = blockIdx.x * 256 + threadIdx.x;
    if (idx >= base * NCHUNK) return;
    int ch = idx / base; int r = idx % base;
    int ox0 = (r % nox) * TOX; int t = r / nox;
    int oy  = t % OH;          t /= OH;
    int oc0 = (t % noc) * TOC; int n = t / noc;
    long ex = n / wdiv;
    const float* wbase = fw + ex * PTOT + woff;
    const float* x     = in + (long)n * in_stride;

    float acc[TOC][TOX];
#pragma unroll
    for (int i = 0; i < TOC; i++)
#pragma unroll
        for (int j = 0; j < TOX; j++) acc[i][j] = 0.f;

    int ixb = ox0 * S - 1;
    int ic0 = ch * ICH;
    for (int ic = ic0; ic < ic0 + ICH; ic++) {
        const float* xc = x + (long)ic * IH * IW;
#pragma unroll
        for (int ky = 0; ky < 3; ky++) {
            int iy = oy * S - 1 + ky;
            if ((unsigned)iy >= (unsigned)IH) continue;
            const float* xr = xc + iy * IW;
            float xv[XLEN];
#pragma unroll
            for (int u = 0; u < XLEN; u++) {
                int ix = ixb + u;
                xv[u] = ((unsigned)ix < (unsigned)IW) ? xr[ix] : 0.f;
            }
#pragma unroll
            for (int i = 0; i < TOC; i++) {
                const float* wp = wbase + ((long)(oc0 + i) * IC + ic) * 9 + ky * 3;
                float w0 = wp[0], w1 = wp[1], w2 = wp[2];
#pragma unroll
                for (int j = 0; j < TOX; j++)
                    acc[i][j] = fmaf(w0, xv[j * S],
                                fmaf(w1, xv[j * S + 1],
                                fmaf(w2, xv[j * S + 2], acc[i][j])));
            }
        }
    }
#pragma unroll
    for (int i = 0; i < TOC; i++) {
        float* op = out + (((long)n * OC + oc0 + i) * OH + oy) * OW + ox0;
#pragma unroll
        for (int j = 0; j < TOX; j++) atomicAdd(op + j, acc[i][j]);
    }
}

__global__ void k_biasrelu(float* __restrict__ out, const float* __restrict__ fw,
                           int boff, int wdiv, int N, int OC, int OHW)
{
    int i = blockIdx.x * 256 + threadIdx.x;
    if (i >= N * OC * OHW) return;
    int oc = (i / OHW) % OC;
    long ex = (i / (OC * OHW)) / wdiv;
    out[i] = fmaxf(out[i] + fw[ex * PTOT + boff + oc], 0.f);
}

__global__ void k_gate(const float* __restrict__ a, const float* __restrict__ gate, int gstride,
                       float* __restrict__ o, int N)
{
    int i = blockIdx.x * 256 + threadIdx.x;
    if (i >= N * FEAT) return;
    int n = i / FEAT, m = i % FEAT;
    o[i] = a[i] * gate[(long)n * gstride + m];
}

__global__ void k_logit_init(const float* __restrict__ fw, int wdiv, float* __restrict__ logits, int N)
{
    int i = blockIdx.x * 256 + threadIdx.x;
    if (i >= N * NCLS) return;
    int cls = i % NCLS;
    long ex = (i / NCLS) / wdiv;
    logits[i] = fw[ex * PTOT + OFF_BO + cls];
}

__global__ void k_head_fwd_chunk(const float* __restrict__ feat, const float* __restrict__ fw,
                                 int wdiv, float* __restrict__ logits, int N)
{
    int gt = blockIdx.x * 256 + threadIdx.x;
    int warp = gt >> 5, lane = gt & 31;
    if (warp >= N * NCLS * 4) return;
    int ch = warp & 3; int w2 = warp >> 2;
    int cls = w2 % NCLS, n = w2 / NCLS;
    long ex = n / wdiv;
    const float* w = fw + ex * PTOT + OFF_WO + (long)cls * FEAT + ch * 1024;
    const float* f = feat + (long)n * FEAT + ch * 1024;
    float acc = 0.f;
#pragma unroll 8
    for (int m = lane; m < 1024; m += 32) acc = fmaf(w[m], f[m], acc);
#pragma unroll
    for (int o = 16; o; o >>= 1) acc += __shfl_down_sync(0xffffffffu, acc, o);
    if (!lane) atomicAdd(&logits[w2], acc);
}

__global__ void k_loss_eval(const float* __restrict__ logits, const int* __restrict__ y,
                            const float* __restrict__ log_lr, float* __restrict__ out)
{
    int e = blockIdx.x, tid = threadIdx.x;
    __shared__ float rv[128];
    __shared__ int   ri[128];
    float v = (tid < NCLS) ? logits[e * NCLS + tid] : -1e30f;
    rv[tid] = v; ri[tid] = tid; __syncthreads();
    for (int s = 64; s > 0; s >>= 1) {
        if (tid < s) {
            if (rv[tid + s] > rv[tid] || (rv[tid + s] == rv[tid] && ri[tid + s] < ri[tid])) {
                rv[tid] = rv[tid + s]; ri[tid] = ri[tid + s];
            }
        }
        __syncthreads();
    }
    float m = rv[0]; int amax = ri[0]; __syncthreads();
    float ex = (tid < NCLS) ? expf(v - m) : 0.f;
    rv[tid] = ex; __syncthreads();
    for (int s = 64; s > 0; s >>= 1) { if (tid < s) rv[tid] += rv[tid + s]; __syncthreads(); }
    if (tid == 0) {
        float lse = m + logf(rv[0]);
        int label = y[e];
        out[e]        = lse - logits[e * NCLS + label];
        out[129 + e]  = (amax == label) ? 1.f : 0.f;
        if (e == 0) out[128] = expf(*log_lr);
    }
}

// ---------------- launcher ----------------
struct LC { int ic, oc, ih, iw, oh, ow, s; };
static const LC lc[5] = {
    {  3,  32, 64, 64, 64, 64, 1},
    { 32,  64, 64, 64, 32, 32, 2},
    { 64, 128, 32, 32, 16, 16, 2},
    {128, 256, 16, 16,  8,  8, 2},
    {256, 256,  8,  8,  4,  4, 2},
};
static const int woffs[5] = {OFF_W0, OFF_W1, OFF_W2, OFF_W3, OFF_W4};
static const int boffs[5] = {OFF_B0, OFF_B1, OFF_B2, OFF_B3, OFF_B4};

static inline unsigned GRID(long n) { return (unsigned)((n + 255) / 256); }

extern "C" void kernel_launch(void* const* d_in, const int* in_sizes, int n_in,
                              void* d_out, int out_size)
{
    const float* pw[12];
    for (int i = 0; i < 12; i++) pw[i] = (const float*)d_in[i];
    const float* log_lr     = (const float*)d_in[12];
    const float* train_x    = (const float*)d_in[13];
    const float* test_x     = (const float*)d_in[14];
    const float* train_gate = (const float*)d_in[15];
    const float* test_gate  = (const float*)d_in[16];
    const int*   train_y    = (const int*)d_in[17];
    const int*   test_y     = (const int*)d_in[18];
    float* out = (float*)d_out;

    float *fw, *ta, *tb;
    cudaGetSymbolAddress((void**)&fw, g_fw);
    cudaGetSymbolAddress((void**)&ta, g_ta);
    cudaGetSymbolAddress((void**)&tb, g_tb);

    // -------- the whole inner loop: ONE persistent kernel --------
    k_inner<<<GRIDN, 256>>>(pw[0], pw[1], pw[2], pw[3], pw[4], pw[5], pw[6], pw[7],
                            pw[8], pw[9], pw[10], pw[11],
                            log_lr, train_x, train_gate, train_y);

    // -------- test forward (ample parallelism; separate launches) --------
    auto fwd_test = [&](int j, const float* in, float* o) {
        const LC& L = lc[j];
        long osz = (long)NTEST * L.oc * L.oh * L.ow;
        cudaMemsetAsync(o, 0, osz * sizeof(float));
        int ich = 32, nch = L.ic / ich;
        long instr = (long)L.ic * L.ih * L.iw;
        long tot = (long)NTEST * (L.oc / 8) * L.oh * (L.ow / 4) * nch;
        k_conv_fwd_chunk<2, 8, 4><<<GRID(tot), 256>>>(in, instr, fw, woffs[j], NL, o,
            NTEST, L.ic, L.oc, L.ih, L.iw, L.oh, L.ow, nch, ich);
        k_biasrelu<<<GRID(osz), 256>>>(o, fw, boffs[j], NL, NTEST, L.oc, L.oh * L.ow);
    };

    {
        long tot = (long)NTEST * (32 / 4) * 64 * (64 / 4);
        k_conv_fwd_t<1, 4, 4><<<GRID(tot), 256>>>(test_x, (long)CHW, fw, OFF_W0, OFF_B0, NL, ta,
                                                  NTEST, 3, 32, 64, 64, 64, 64);
    }
    {
        long tot = (long)NTEST * (64 / 8) * 32 * (32 / 4);
        k_conv_fwd_t<2, 8, 4><<<GRID(tot), 256>>>(ta, (long)32 * 64 * 64, fw, OFF_W1, OFF_B1, NL, tb,
                                                  NTEST, 32, 64, 64, 64, 32, 32);
    }
    fwd_test(2, tb, ta);
    fwd_test(3, ta, tb);
    fwd_test(4, tb, ta);
    k_gate<<<GRID((long)NTEST * FEAT), 256>>>(ta, test_gate, FEAT, tb, NTEST);
    k_logit_init<<<GRID((long)NTEST * NCLS), 256>>>(fw, NL, out + 257, NTEST);
    k_head_fwd_chunk<<<GRID((long)NTEST * NCLS * 4 * 32), 256>>>(tb, fw, NL, out + 257, NTEST);
    k_loss_eval<<<NTEST, 128>>>(out + 257, test_y, log_lr, out);
}

// round 9
// speedup vs baseline: 1.5951x; 1.5951x over previous
#include <cuda_runtime.h>

// ---------------- problem constants ----------------
constexpr int NB    = 8;
constexpr int NT    = 5;
constexpr int NL    = 16;
constexpr int NTEST = NB * NL;          // 128
constexpr int NCLS  = 100;
constexpr int FEAT  = 4096;
constexpr int CHW   = 3 * 64 * 64;

constexpr int OFF_W0 = 0;        constexpr int SZ_W0 = 32 * 3 * 9;
constexpr int OFF_B0 = 864;      constexpr int SZ_B0 = 32;
constexpr int OFF_W1 = 896;      constexpr int SZ_W1 = 64 * 32 * 9;
constexpr int OFF_B1 = 19328;    constexpr int SZ_B1 = 64;
constexpr int OFF_W2 = 19392;    constexpr int SZ_W2 = 128 * 64 * 9;
constexpr int OFF_B2 = 93120;    constexpr int SZ_B2 = 128;
constexpr int OFF_W3 = 93248;    constexpr int SZ_W3 = 256 * 128 * 9;
constexpr int OFF_B3 = 388160;   constexpr int SZ_B3 = 256;
constexpr int OFF_W4 = 388416;   constexpr int SZ_W4 = 256 * 256 * 9;
constexpr int OFF_B4 = 978240;   constexpr int SZ_B4 = 256;
constexpr int OFF_WO = 978496;   constexpr int SZ_WO = NCLS * FEAT;
constexpr int OFF_BO = 1388096;  constexpr int SZ_BO = NCLS;
constexpr int PTOT   = 1388196;

// ---------------- static device scratch ----------------
__device__ float g_fw  [NB * PTOT];
__device__ float g_a1[NB * 131072];
__device__ float g_a2[NB * 65536];
__device__ float g_a3[NB * 32768];
__device__ float g_a4[NB * 16384];
__device__ float g_a5[NB * 4096];
__device__ float g_feat[NB * FEAT];
__device__ float g_logit[NB * NCLS];
__device__ float g_dlogit[NB * NCLS];
__device__ float g_d1[NB * 131072];
__device__ float g_d2[NB * 131072];
__device__ float g_ta[NTEST * 131072];
__device__ float g_tb[NTEST * 131072];

// ---------------- kernels ----------------
// single fused broadcast of all 12 params into per-task fast weights
__global__ void k_bcast_all(const float* __restrict__ w0, const float* __restrict__ b0,
                            const float* __restrict__ w1, const float* __restrict__ b1,
                            const float* __restrict__ w2, const float* __restrict__ b2,
                            const float* __restrict__ w3, const float* __restrict__ b3,
                            const float* __restrict__ w4, const float* __restrict__ b4,
                            const float* __restrict__ wo, const float* __restrict__ bo,
                            float* __restrict__ fw)
{
    long i = blockIdx.x * 256L + threadIdx.x;
    if (i >= (long)NB * PTOT) return;
    int j = (int)(i % PTOT);
    const float* src; int off;
    if      (j < OFF_B0) { src = w0; off = OFF_W0; }
    else if (j < OFF_W1) { src = b0; off = OFF_B0; }
    else if (j < OFF_B1) { src = w1; off = OFF_W1; }
    else if (j < OFF_W2) { src = b1; off = OFF_B1; }
    else if (j < OFF_B2) { src = w2; off = OFF_W2; }
    else if (j < OFF_W3) { src = b2; off = OFF_B2; }
    else if (j < OFF_B3) { src = w3; off = OFF_W3; }
    else if (j < OFF_W4) { src = b3; off = OFF_B3; }
    else if (j < OFF_B4) { src = w4; off = OFF_W4; }
    else if (j < OFF_WO) { src = b4; off = OFF_B4; }
    else if (j < OFF_BO) { src = wo; off = OFF_WO; }
    else                 { src = bo; off = OFF_BO; }
    fw[i] = src[j - off];
}

// Direct tiled conv fwd with fused bias+relu.
template<int S, int TOC, int TOX>
__global__ void k_conv_fwd_t(const float* __restrict__ in, long in_stride,
                             const float* __restrict__ fw, int woff, int boff, int wdiv,
                             float* __restrict__ out,
                             int N, int IC, int OC, int IH, int IW, int OH, int OW)
{
    constexpr int XLEN = (TOX - 1) * S + 3;
    int idx = blockIdx.x * 256 + threadIdx.x;
    int nox = OW / TOX;
    int noc = OC / TOC;
    if (idx >= N * noc * OH * nox) return;
    int ox0 = (idx % nox) * TOX; int t = idx / nox;
    int oy  = t % OH;            t /= OH;
    int oc0 = (t % noc) * TOC;   int n = t / noc;
    long ex = n / wdiv;
    const float* wbase = fw + ex * PTOT + woff;
    const float* x     = in + (long)n * in_stride;

    float acc[TOC][TOX];
#pragma unroll
    for (int i = 0; i < TOC; i++) {
        float bv = fw[ex * PTOT + boff + oc0 + i];
#pragma unroll
        for (int j = 0; j < TOX; j++) acc[i][j] = bv;
    }
    int ixb = ox0 * S - 1;
    for (int ic = 0; ic < IC; ic++) {
        const float* xc = x + (long)ic * IH * IW;
#pragma unroll
        for (int ky = 0; ky < 3; ky++) {
            int iy = oy * S - 1 + ky;
            if ((unsigned)iy >= (unsigned)IH) continue;
            const float* xr = xc + iy * IW;
            float xv[XLEN];
#pragma unroll
            for (int u = 0; u < XLEN; u++) {
                int ix = ixb + u;
                xv[u] = ((unsigned)ix < (unsigned)IW) ? xr[ix] : 0.f;
            }
#pragma unroll
            for (int i = 0; i < TOC; i++) {
                const float* wp = wbase + ((long)(oc0 + i) * IC + ic) * 9 + ky * 3;
                float w0 = wp[0], w1 = wp[1], w2 = wp[2];
#pragma unroll
                for (int j = 0; j < TOX; j++)
                    acc[i][j] = fmaf(w0, xv[j * S],
                                fmaf(w1, xv[j * S + 1],
                                fmaf(w2, xv[j * S + 2], acc[i][j])));
            }
        }
    }
#pragma unroll
    for (int i = 0; i < TOC; i++) {
        float* op = out + (((long)n * OC + oc0 + i) * OH + oy) * OW + ox0;
#pragma unroll
        for (int j = 0; j < TOX; j++) op[j] = fmaxf(acc[i][j], 0.f);
    }
}

// IC-chunked conv fwd: atomic partial sums into zeroed out buffer.
template<int S, int TOC, int TOX>
__global__ void k_conv_fwd_chunk(const float* __restrict__ in, long in_stride,
                                 const float* __restrict__ fw, int woff, int wdiv,
                                 float* __restrict__ out,
                                 int N, int IC, int OC, int IH, int IW, int OH, int OW,
                                 int NCHUNK, int ICH)
{
    constexpr int XLEN = (TOX - 1) * S + 3;
    int nox = OW / TOX;
    int noc = OC / TOC;
    int base = N * noc * OH * nox;
    int idx = blockIdx.x * 256 + threadIdx.x;
    if (idx >= base * NCHUNK) return;
    int ch = idx / base; int r = idx % base;
    int ox0 = (r % nox) * TOX; int t = r / nox;
    int oy  = t % OH;          t /= OH;
    int oc0 = (t % noc) * TOC; int n = t / noc;
    long ex = n / wdiv;
    const float* wbase = fw + ex * PTOT + woff;
    const float* x     = in + (long)n * in_stride;

    float acc[TOC][TOX];
#pragma unroll
    for (int i = 0; i < TOC; i++)
#pragma unroll
        for (int j = 0; j < TOX; j++) acc[i][j] = 0.f;

    int ixb = ox0 * S - 1;
    int ic0 = ch * ICH;
    for (int ic = ic0; ic < ic0 + ICH; ic++) {
        const float* xc = x + (long)ic * IH * IW;
#pragma unroll
        for (int ky = 0; ky < 3; ky++) {
            int iy = oy * S - 1 + ky;
            if ((unsigned)iy >= (unsigned)IH) continue;
            const float* xr = xc + iy * IW;
            float xv[XLEN];
#pragma unroll
            for (int u = 0; u < XLEN; u++) {
                int ix = ixb + u;
                xv[u] = ((unsigned)ix < (unsigned)IW) ? xr[ix] : 0.f;
            }
#pragma unroll
            for (int i = 0; i < TOC; i++) {
                const float* wp = wbase + ((long)(oc0 + i) * IC + ic) * 9 + ky * 3;
                float w0 = wp[0], w1 = wp[1], w2 = wp[2];
#pragma unroll
                for (int j = 0; j < TOX; j++)
                    acc[i][j] = fmaf(w0, xv[j * S],
                                fmaf(w1, xv[j * S + 1],
                                fmaf(w2, xv[j * S + 2], acc[i][j])));
            }
        }
    }
#pragma unroll
    for (int i = 0; i < TOC; i++) {
        float* op = out + (((long)n * OC + oc0 + i) * OH + oy) * OW + ox0;
#pragma unroll
        for (int j = 0; j < TOX; j++) atomicAdd(op + j, acc[i][j]);
    }
}

// in-place: out = relu(out + bias[oc])
__global__ void k_biasrelu(float* __restrict__ out, const float* __restrict__ fw,
                           int boff, int wdiv, int N, int OC, int OHW)
{
    int i = blockIdx.x * 256 + threadIdx.x;
    if (i >= N * OC * OHW) return;
    int oc = (i / OHW) % OC;
    long ex = (i / (OC * OHW)) / wdiv;
    out[i] = fmaxf(out[i] + fw[ex * PTOT + boff + oc], 0.f);
}

__global__ void k_gate(const float* __restrict__ a, const float* __restrict__ gate, int gstride,
                       float* __restrict__ o, int N)
{
    int i = blockIdx.x * 256 + threadIdx.x;
    if (i >= N * FEAT) return;
    int n = i / FEAT, m = i % FEAT;
    o[i] = a[i] * gate[(long)n * gstride + m];
}

// logits[n,cls] = b_out[cls]
__global__ void k_logit_init(const float* __restrict__ fw, int wdiv, float* __restrict__ logits, int N)
{
    int i = blockIdx.x * 256 + threadIdx.x;
    if (i >= N * NCLS) return;
    int cls = i % NCLS;
    long ex = (i / NCLS) / wdiv;
    logits[i] = fw[ex * PTOT + OFF_BO + cls];
}

// FEAT-chunked head fwd: one warp per (n, cls, chunk of 1024); atomicAdd partial dot.
__global__ void k_head_fwd_chunk(const float* __restrict__ feat, const float* __restrict__ fw,
                                 int wdiv, float* __restrict__ logits, int N)
{
    int gt = blockIdx.x * 256 + threadIdx.x;
    int warp = gt >> 5, lane = gt & 31;
    if (warp >= N * NCLS * 4) return;
    int ch = warp & 3; int w2 = warp >> 2;
    int cls = w2 % NCLS, n = w2 / NCLS;
    long ex = n / wdiv;
    const float* w = fw + ex * PTOT + OFF_WO + (long)cls * FEAT + ch * 1024;
    const float* f = feat + (long)n * FEAT + ch * 1024;
    float acc = 0.f;
#pragma unroll 8
    for (int m = lane; m < 1024; m += 32) acc = fmaf(w[m], f[m], acc);
#pragma unroll
    for (int o = 16; o; o >>= 1) acc += __shfl_down_sync(0xffffffffu, acc, o);
    if (!lane) atomicAdd(&logits[w2], acc);
}

// dlogit = softmax - onehot; also updates b_out in place.
__global__ void k_ce_grad(const float* __restrict__ logits, const int* __restrict__ y,
                          int ystride, int yoff, float* __restrict__ dlogit,
                          float* __restrict__ fw, const float* __restrict__ log_lr)
{
    int b = blockIdx.x, tid = threadIdx.x;
    __shared__ float red[128];
    float v = (tid < NCLS) ? logits[b * NCLS + tid] : -1e30f;
    red[tid] = v; __syncthreads();
    for (int s = 64; s > 0; s >>= 1) { if (tid < s) red[tid] = fmaxf(red[tid], red[tid + s]); __syncthreads(); }
    float m = red[0]; __syncthreads();
    float e = (tid < NCLS) ? expf(v - m) : 0.f;
    red[tid] = e; __syncthreads();
    for (int s = 64; s > 0; s >>= 1) { if (tid < s) red[tid] += red[tid + s]; __syncthreads(); }
    float sum = red[0];
    int label = y[b * ystride + yoff];
    if (tid < NCLS) {
        float dl = e / sum - (tid == label ? 1.f : 0.f);
        dlogit[b * NCLS + tid] = dl;
        fw[(long)b * PTOT + OFF_BO + tid] -= expf(*log_lr) * dl;
    }
}

// NCLS-chunked head bwd to features: atomicAdd raw partial (no gate/mask yet).
__global__ void k_head_bwd_f_chunk(const float* __restrict__ dlogit, const float* __restrict__ fw,
                                   float* __restrict__ raw)
{
    int i = blockIdx.x * 256 + threadIdx.x;
    if (i >= NB * 4 * FEAT) return;
    int m = i % FEAT; int t = i / FEAT;
    int ch = t % 4; int b = t / 4;
    const float* w  = fw + (long)b * PTOT + OFF_WO + m + (long)(ch * 25) * FEAT;
    const float* dl = dlogit + b * NCLS + ch * 25;
    float acc = 0.f;
#pragma unroll
    for (int n = 0; n < 25; n++) acc = fmaf(w[(long)n * FEAT], dl[n], acc);
    atomicAdd(&raw[(long)b * FEAT + m], acc);
}

// dz = (a5>0) ? raw*gate : 0
__global__ void k_mask_gate(const float* __restrict__ raw, const float* __restrict__ a5,
                            const float* __restrict__ gate, int gstride, float* __restrict__ dz)
{
    int i = blockIdx.x * 256 + threadIdx.x;
    if (i >= NB * FEAT) return;
    int m = i % FEAT, b = i / FEAT;
    dz[i] = (a5[i] > 0.f) ? raw[i] * gate[(long)b * gstride + m] : 0.f;
}

// W_out -= lr * dlogit ⊗ feat
__global__ void k_head_upd_w(const float* __restrict__ dlogit, const float* __restrict__ feat,
                             float* __restrict__ fw, const float* __restrict__ log_lr)
{
    int i = blockIdx.x * 256 + threadIdx.x;
    if (i >= NB * NCLS * FEAT) return;
    int m = i % FEAT; int t = i / FEAT;
    int cls = t % NCLS; int b = t / NCLS;
    fw[(long)b * PTOT + OFF_WO + (long)cls * FEAT + m] -=
        expf(*log_lr) * dlogit[b * NCLS + cls] * feat[(long)b * FEAT + m];
}

// bias_j -= lr * sum(dz); one warp per (b, oc)
__global__ void k_bwd_b_upd(const float* __restrict__ dz, float* __restrict__ fw,
                            const float* __restrict__ log_lr, int boff, int OC, int OHW)
{
    int gt = blockIdx.x * 256 + threadIdx.x;
    int warp = gt >> 5, lane = gt & 31;
    if (warp >= NB * OC) return;
    int oc = warp % OC, b = warp / OC;
    const float* p = dz + ((long)b * OC + oc) * OHW;
    float acc = 0.f;
    for (int i = lane; i < OHW; i += 32) acc += p[i];
#pragma unroll
    for (int o = 16; o; o >>= 1) acc += __shfl_down_sync(0xffffffffu, acc, o);
    if (!lane) fw[(long)b * PTOT + boff + oc] -= expf(*log_lr) * acc;
}

// WARP-COOPERATIVE weight grad + fused SGD.
// One warp per (b, oc, ic, oy-chunk); lanes sweep consecutive (oy,ox) pixels.
// z-loads coalesced, x-loads stride-S. 9 accs -> warp reduce -> 9 fused-SGD atomics.
template<int S>
__global__ void k_bwd_w_warp(const float* __restrict__ dz, const float* __restrict__ xin, long xstride,
                             float* __restrict__ fw, const float* __restrict__ log_lr, int woff,
                             int IC, int OC, int IH, int IW, int OH, int OW, int NCH)
{
    long gt = blockIdx.x * 256L + threadIdx.x;
    long w = gt >> 5; int lane = (int)(gt & 31);
    if (w >= (long)NB * OC * IC * NCH) return;
    int c  = (int)(w % NCH); long t = w / NCH;
    int ic = (int)(t % IC); t /= IC;
    int oc = (int)(t % OC); int b = (int)(t / OC);
    int CH = OH / NCH;
    const float* x = xin + (long)b * xstride + (long)ic * IH * IW;
    const float* z = dz + ((long)b * OC + oc) * OH * OW;
    float acc[9];
#pragma unroll
    for (int k = 0; k < 9; k++) acc[k] = 0.f;
    int oybase = c * CH;
    int npix = CH * OW;
    for (int p = lane; p < npix; p += 32) {
        int oy = oybase + p / OW;
        int ox = p % OW;
        float zv = z[oy * OW + ox];
#pragma unroll
        for (int ky = 0; ky < 3; ky++) {
            int iy = oy * S + ky - 1;
            if ((unsigned)iy >= (unsigned)IH) continue;
            const float* xr = x + iy * IW;
            int ixb = ox * S - 1;
#pragma unroll
            for (int kx = 0; kx < 3; kx++) {
                int ix = ixb + kx;
                if ((unsigned)ix < (unsigned)IW)
                    acc[ky * 3 + kx] = fmaf(zv, xr[ix], acc[ky * 3 + kx]);
            }
        }
    }
    float nlr = -expf(*log_lr);
    float* g = fw + (long)b * PTOT + woff + ((long)oc * IC + ic) * 9;
#pragma unroll
    for (int k = 0; k < 9; k++) {
        float v = acc[k];
#pragma unroll
        for (int o = 16; o; o >>= 1) v += __shfl_down_sync(0xffffffffu, v, o);
        if (!lane) atomicAdd(g + k, nlr * v);
    }
}

// OC-chunked bwd_x (stride-2): atomicAdd raw dx for 4 consecutive pixels.
__global__ void k_bwd_x_chunk(const float* __restrict__ dz, const float* __restrict__ fw, int woff,
                              float* __restrict__ raw,
                              int IC, int OC, int IH, int IW, int OH, int OW,
                              int NCHUNK, int OCH)
{
    int nix = IW >> 2;
    int base = NB * IC * IH * nix;
    int idx = blockIdx.x * 256 + threadIdx.x;
    if (idx >= base * NCHUNK) return;
    int ch = idx / base; int r = idx % base;
    int ix0 = (r % nix) * 4; int t = r / nix;
    int iy = t % IH; t /= IH;
    int ic = t % IC; int b = t / IC;
    long pix = (((long)b * IC + ic) * IH + iy) * IW + ix0;

    float acc0 = 0.f, acc1 = 0.f, acc2 = 0.f, acc3 = 0.f;
    int ox0p = ix0 >> 1;
    bool ok2 = (ox0p + 2 < OW), ok1 = (ox0p + 1 < OW);

    int oyv[3]; bool kyok[3];
#pragma unroll
    for (int ky = 0; ky < 3; ky++) {
        int ty = iy + 1 - ky;
        kyok[ky] = (ty >= 0) && !(ty & 1) && ((ty >> 1) < OH);
        oyv[ky] = ty >> 1;
    }
    const float* wb = fw + (long)b * PTOT + woff + (long)ic * 9;
    const float* zb = dz + (long)b * OC * OH * OW;
    int oc0 = ch * OCH;
    for (int oc = oc0; oc < oc0 + OCH; oc++) {
        const float* wp = wb + (long)oc * IC * 9;
        const float* zp = zb + (long)oc * OH * OW;
#pragma unroll
        for (int ky = 0; ky < 3; ky++) {
            if (!kyok[ky]) continue;
            const float* zr = zp + oyv[ky] * OW;
            float d0 = zr[ox0p];
            float d1 = ok1 ? zr[ox0p + 1] : 0.f;
            float d2 = ok2 ? zr[ox0p + 2] : 0.f;
            float wk0 = wp[ky * 3 + 0], wk1 = wp[ky * 3 + 1], wk2 = wp[ky * 3 + 2];
            acc0 = fmaf(wk1, d0, acc0);
            acc1 = fmaf(wk0, d1, fmaf(wk2, d0, acc1));
            acc2 = fmaf(wk1, d1, acc2);
            acc3 = fmaf(wk0, d2, fmaf(wk2, d1, acc3));
        }
    }
    atomicAdd(&raw[pix],     acc0);
    atomicAdd(&raw[pix + 1], acc1);
    atomicAdd(&raw[pix + 2], acc2);
    atomicAdd(&raw[pix + 3], acc3);
}

// dz = (act>0) ? raw : 0
__global__ void k_mask(const float* __restrict__ raw, const float* __restrict__ act,
                       float* __restrict__ dz, int count)
{
    int i = blockIdx.x * 256 + threadIdx.x;
    if (i < count) dz[i] = (act[i] > 0.f) ? raw[i] : 0.f;
}

__global__ void k_loss_eval(const float* __restrict__ logits, const int* __restrict__ y,
                            const float* __restrict__ log_lr, float* __restrict__ out)
{
    int e = blockIdx.x, tid = threadIdx.x;
    __shared__ float rv[128];
    __shared__ int   ri[128];
    float v = (tid < NCLS) ? logits[e * NCLS + tid] : -1e30f;
    rv[tid] = v; ri[tid] = tid; __syncthreads();
    for (int s = 64; s > 0; s >>= 1) {
        if (tid < s) {
            if (rv[tid + s] > rv[tid] || (rv[tid + s] == rv[tid] && ri[tid + s] < ri[tid])) {
                rv[tid] = rv[tid + s]; ri[tid] = ri[tid + s];
            }
        }
        __syncthreads();
    }
    float m = rv[0]; int amax = ri[0]; __syncthreads();
    float ex = (tid < NCLS) ? expf(v - m) : 0.f;
    rv[tid] = ex; __syncthreads();
    for (int s = 64; s > 0; s >>= 1) { if (tid < s) rv[tid] += rv[tid + s]; __syncthreads(); }
    if (tid == 0) {
        float lse = m + logf(rv[0]);
        int label = y[e];
        out[e]        = lse - logits[e * NCLS + label];
        out[129 + e]  = (amax == label) ? 1.f : 0.f;
        if (e == 0) out[128] = expf(*log_lr);
    }
}

// ---------------- launcher ----------------
struct LC { int ic, oc, ih, iw, oh, ow, s; };
static const LC lc[5] = {
    {  3,  32, 64, 64, 64, 64, 1},
    { 32,  64, 64, 64, 32, 32, 2},
    { 64, 128, 32, 32, 16, 16, 2},
    {128, 256, 16, 16,  8,  8, 2},
    {256, 256,  8,  8,  4,  4, 2},
};
static const int woffs[5] = {OFF_W0, OFF_W1, OFF_W2, OFF_W3, OFF_W4};
static const int boffs[5] = {OFF_B0, OFF_B1, OFF_B2, OFF_B3, OFF_B4};

static inline unsigned GRID(long n) { return (unsigned)((n + 255) / 256); }

extern "C" void kernel_launch(void* const* d_in, const int* in_sizes, int n_in,
                              void* d_out, int out_size)
{
    const float* pw[12];
    for (int i = 0; i < 12; i++) pw[i] = (const float*)d_in[i];
    const float* log_lr     = (const float*)d_in[12];
    const float* train_x    = (const float*)d_in[13];
    const float* test_x     = (const float*)d_in[14];
    const float* train_gate = (const float*)d_in[15];
    const float* test_gate  = (const float*)d_in[16];
    const int*   train_y    = (const int*)d_in[17];
    const int*   test_y     = (const int*)d_in[18];
    float* out = (float*)d_out;

    float *fw, *a1, *a2, *a3, *a4, *a5, *feat, *logit, *dlogit, *d1, *d2, *ta, *tb;
    cudaGetSymbolAddress((void**)&fw,     g_fw);
    cudaGetSymbolAddress((void**)&a1,     g_a1);
    cudaGetSymbolAddress((void**)&a2,     g_a2);
    cudaGetSymbolAddress((void**)&a3,     g_a3);
    cudaGetSymbolAddress((void**)&a4,     g_a4);
    cudaGetSymbolAddress((void**)&a5,     g_a5);
    cudaGetSymbolAddress((void**)&feat,   g_feat);
    cudaGetSymbolAddress((void**)&logit,  g_logit);
    cudaGetSymbolAddress((void**)&dlogit, g_dlogit);
    cudaGetSymbolAddress((void**)&d1,     g_d1);
    cudaGetSymbolAddress((void**)&d2,     g_d2);
    cudaGetSymbolAddress((void**)&ta,     g_ta);
    cudaGetSymbolAddress((void**)&tb,     g_tb);

    float* acts[6] = {nullptr, a1, a2, a3, a4, a5};

    // inner fwd: IC chunk sizes per layer (layers 1..4)
    const int f_ich[5] = {0, 8, 8, 8, 4};
    // bwd_w: oy chunks per layer (warp-cooperative)
    const int wnch[5] = {16, 4, 2, 1, 1};

    // launch #1: fused broadcast
    k_bcast_all<<<GRID((long)NB * PTOT), 256>>>(pw[0], pw[1], pw[2], pw[3], pw[4], pw[5],
                                                pw[6], pw[7], pw[8], pw[9], pw[10], pw[11], fw);

    auto fwd_inner_conv = [&](int j, const float* in, float* o) {
        const LC& L = lc[j];
        int ich = f_ich[j], nch = L.ic / ich;
        long instr = (long)L.ic * L.ih * L.iw;
        long tot = (long)NB * (L.oc / 4) * L.oh * (L.ow / 4) * nch;
        k_conv_fwd_chunk<2, 4, 4><<<GRID(tot), 256>>>(in, instr, fw, woffs[j], 1, o,
            NB, L.ic, L.oc, L.ih, L.iw, L.oh, L.ow, nch, ich);
        long osz = (long)NB * L.oc * L.oh * L.ow;
        k_biasrelu<<<GRID(osz), 256>>>(o, fw, boffs[j], 1, NB, L.oc, L.oh * L.ow);
    };
    auto bwd_w = [&](int j, const float* dzb, const float* xin, long xstride) {
        const LC& L = lc[j];
        long warps = (long)NB * L.oc * L.ic * wnch[j];
        if (L.s == 2)
            k_bwd_w_warp<2><<<GRID(warps * 32), 256>>>(dzb, xin, xstride, fw, log_lr, woffs[j],
                L.ic, L.oc, L.ih, L.iw, L.oh, L.ow, wnch[j]);
        else
            k_bwd_w_warp<1><<<GRID(warps * 32), 256>>>(dzb, xin, xstride, fw, log_lr, woffs[j],
                L.ic, L.oc, L.ih, L.iw, L.oh, L.ow, wnch[j]);
    };

    // -------- inner loop --------
    for (int t = 0; t < NT; t++) {
        const float* in0 = train_x + (long)t * CHW;
        // forward
        {
            long tot = (long)NB * (32 / 4) * 64 * (64 / 4);
            k_conv_fwd_t<1, 4, 4><<<GRID(tot), 256>>>(in0, (long)NT * CHW, fw, OFF_W0, OFF_B0, 1, a1,
                                                      NB, 3, 32, 64, 64, 64, 64);   // launch #2 (t=0)
        }
        if (t == 0) {
            // hoisted memsets so that launch #6 = inner fwd L1 conv chunk (for ncu -s 5 -c 1)
            cudaMemsetAsync(a2, 0, (long)NB * 65536 * sizeof(float));   // #3
            cudaMemsetAsync(a3, 0, (long)NB * 32768 * sizeof(float));   // #4
            cudaMemsetAsync(a4, 0, (long)NB * 16384 * sizeof(float));   // #5
        } else {
            cudaMemsetAsync(a2, 0, (long)NB * 65536 * sizeof(float));
            cudaMemsetAsync(a3, 0, (long)NB * 32768 * sizeof(float));
            cudaMemsetAsync(a4, 0, (long)NB * 16384 * sizeof(float));
        }
        cudaMemsetAsync(a5, 0, (long)NB * 4096 * sizeof(float));
        fwd_inner_conv(1, a1, a2);          // #6 = k_conv_fwd_chunk (inner L1) on t=0
        fwd_inner_conv(2, a2, a3);
        fwd_inner_conv(3, a3, a4);
        fwd_inner_conv(4, a4, a5);
        k_gate<<<GRID((long)NB * FEAT), 256>>>(a5, train_gate + (long)t * FEAT, NT * FEAT, feat, NB);
        k_logit_init<<<GRID((long)NB * NCLS), 256>>>(fw, 1, logit, NB);
        k_head_fwd_chunk<<<GRID((long)NB * NCLS * 4 * 32), 256>>>(feat, fw, 1, logit, NB);
        // backward (fused SGD)
        k_ce_grad<<<NB, 128>>>(logit, train_y, NT, t, dlogit, fw, log_lr);
        cudaMemsetAsync(d2, 0, (long)NB * FEAT * sizeof(float));
        k_head_bwd_f_chunk<<<GRID((long)NB * 4 * FEAT), 256>>>(dlogit, fw, d2);
        k_mask_gate<<<GRID((long)NB * FEAT), 256>>>(d2, a5, train_gate + (long)t * FEAT, NT * FEAT, d1);
        k_head_upd_w<<<GRID((long)NB * NCLS * FEAT), 256>>>(dlogit, feat, fw, log_lr);

        for (int j = 4; j >= 1; j--) {
            const LC& L = lc[j];
            long insz = (long)NB * L.ic * L.ih * L.iw;
            long instr = (long)L.ic * L.ih * L.iw;
            k_bwd_b_upd<<<GRID((long)NB * L.oc * 32), 256>>>(d1, fw, log_lr, boffs[j],
                                                             L.oc, L.oh * L.ow);
            cudaMemsetAsync(d2, 0, insz * sizeof(float));
            {
                int nch = L.oc / 8;
                long tot = (long)NB * L.ic * L.ih * (L.iw / 4) * nch;
                k_bwd_x_chunk<<<GRID(tot), 256>>>(d1, fw, woffs[j], d2,
                    L.ic, L.oc, L.ih, L.iw, L.oh, L.ow, nch, 8);
            }
            bwd_w(j, d1, acts[j], instr);    // after bwd_x (reads pre-update W_j)
            k_mask<<<GRID(insz), 256>>>(d2, acts[j], d1, (int)insz);
        }
        k_bwd_b_upd<<<GRID((long)NB * 32 * 32), 256>>>(d1, fw, log_lr, OFF_B0, 32, 64 * 64);
        bwd_w(0, d1, in0, (long)NT * CHW);
    }

    // -------- test forward --------
    auto fwd_test = [&](int j, const float* in, float* o) {
        const LC& L = lc[j];
        long osz = (long)NTEST * L.oc * L.oh * L.ow;
        cudaMemsetAsync(o, 0, osz * sizeof(float));
        int ich = 32, nch = L.ic / ich;
        long instr = (long)L.ic * L.ih * L.iw;
        long tot = (long)NTEST * (L.oc / 8) * L.oh * (L.ow / 4) * nch;
        k_conv_fwd_chunk<2, 8, 4><<<GRID(tot), 256>>>(in, instr, fw, woffs[j], NL, o,
            NTEST, L.ic, L.oc, L.ih, L.iw, L.oh, L.ow, nch, ich);
        k_biasrelu<<<GRID(osz), 256>>>(o, fw, boffs[j], NL, NTEST, L.oc, L.oh * L.ow);
    };

    {
        long tot = (long)NTEST * (32 / 4) * 64 * (64 / 4);
        k_conv_fwd_t<1, 4, 4><<<GRID(tot), 256>>>(test_x, (long)CHW, fw, OFF_W0, OFF_B0, NL, ta,
                                                  NTEST, 3, 32, 64, 64, 64, 64);
    }
    {
        long tot = (long)NTEST * (64 / 8) * 32 * (32 / 4);
        k_conv_fwd_t<2, 8, 4><<<GRID(tot), 256>>>(ta, (long)32 * 64 * 64, fw, OFF_W1, OFF_B1, NL, tb,
                                                  NTEST, 32, 64, 64, 64, 32, 32);
    }
    fwd_test(2, tb, ta);
    fwd_test(3, ta, tb);
    fwd_test(4, tb, ta);
    k_gate<<<GRID((long)NTEST * FEAT), 256>>>(ta, test_gate, FEAT, tb, NTEST);
    k_logit_init<<<GRID((long)NTEST * NCLS), 256>>>(fw, NL, out + 257, NTEST);
    k_head_fwd_chunk<<<GRID((long)NTEST * NCLS * 4 * 32), 256>>>(tb, fw, NL, out + 257, NTEST);
    k_loss_eval<<<NTEST, 128>>>(out + 257, test_y, log_lr, out);
}

// round 10
// speedup vs baseline: 1.6361x; 1.0257x over previous
#include <cuda_runtime.h>

// ---------------- problem constants ----------------
constexpr int NB    = 8;
constexpr int NT    = 5;
constexpr int NL    = 16;
constexpr int NTEST = NB * NL;          // 128
constexpr int NCLS  = 100;
constexpr int FEAT  = 4096;
constexpr int CHW   = 3 * 64 * 64;

constexpr int OFF_W0 = 0;        constexpr int SZ_W0 = 32 * 3 * 9;
constexpr int OFF_B0 = 864;      constexpr int SZ_B0 = 32;
constexpr int OFF_W1 = 896;      constexpr int SZ_W1 = 64 * 32 * 9;
constexpr int OFF_B1 = 19328;    constexpr int SZ_B1 = 64;
constexpr int OFF_W2 = 19392;    constexpr int SZ_W2 = 128 * 64 * 9;
constexpr int OFF_B2 = 93120;    constexpr int SZ_B2 = 128;
constexpr int OFF_W3 = 93248;    constexpr int SZ_W3 = 256 * 128 * 9;
constexpr int OFF_B3 = 388160;   constexpr int SZ_B3 = 256;
constexpr int OFF_W4 = 388416;   constexpr int SZ_W4 = 256 * 256 * 9;
constexpr int OFF_B4 = 978240;   constexpr int SZ_B4 = 256;
constexpr int OFF_WO = 978496;   constexpr int SZ_WO = NCLS * FEAT;
constexpr int OFF_BO = 1388096;  constexpr int SZ_BO = NCLS;
constexpr int PTOT   = 1388196;

// ---------------- static device scratch ----------------
__device__ float g_fw  [NB * PTOT];
__device__ float g_a1[NB * 131072];
__device__ float g_a2[NB * 65536];
__device__ float g_a3[NB * 32768];
__device__ float g_a4[NB * 16384];
__device__ float g_a5[NB * 4096];
__device__ float g_feat[NB * FEAT];
__device__ float g_logit[NB * NCLS];
__device__ float g_dlogit[NB * NCLS];
__device__ float g_d1[NB * 131072];
__device__ float g_d2[NB * 131072];
__device__ float g_ta[NTEST * 131072];
__device__ float g_tb[NTEST * 131072];

// ---------------- kernels ----------------
__global__ void k_bcast_all(const float* __restrict__ w0, const float* __restrict__ b0,
                            const float* __restrict__ w1, const float* __restrict__ b1,
                            const float* __restrict__ w2, const float* __restrict__ b2,
                            const float* __restrict__ w3, const float* __restrict__ b3,
                            const float* __restrict__ w4, const float* __restrict__ b4,
                            const float* __restrict__ wo, const float* __restrict__ bo,
                            float* __restrict__ fw)
{
    long i = blockIdx.x * 256L + threadIdx.x;
    if (i >= (long)NB * PTOT) return;
    int j = (int)(i % PTOT);
    const float* src; int off;
    if      (j < OFF_B0) { src = w0; off = OFF_W0; }
    else if (j < OFF_W1) { src = b0; off = OFF_B0; }
    else if (j < OFF_B1) { src = w1; off = OFF_W1; }
    else if (j < OFF_W2) { src = b1; off = OFF_B1; }
    else if (j < OFF_B2) { src = w2; off = OFF_W2; }
    else if (j < OFF_W3) { src = b2; off = OFF_B2; }
    else if (j < OFF_B3) { src = w3; off = OFF_W3; }
    else if (j < OFF_W4) { src = b3; off = OFF_B3; }
    else if (j < OFF_B4) { src = w4; off = OFF_W4; }
    else if (j < OFF_WO) { src = b4; off = OFF_B4; }
    else if (j < OFF_BO) { src = wo; off = OFF_WO; }
    else                 { src = bo; off = OFF_BO; }
    fw[i] = src[j - off];
}

// Direct tiled conv fwd with fused bias+relu.
template<int S, int TOC, int TOX>
__global__ void k_conv_fwd_t(const float* __restrict__ in, long in_stride,
                             const float* __restrict__ fw, int woff, int boff, int wdiv,
                             float* __restrict__ out,
                             int N, int IC, int OC, int IH, int IW, int OH, int OW)
{
    constexpr int XLEN = (TOX - 1) * S + 3;
    int idx = blockIdx.x * 256 + threadIdx.x;
    int nox = OW / TOX;
    int noc = OC / TOC;
    if (idx >= N * noc * OH * nox) return;
    int ox0 = (idx % nox) * TOX; int t = idx / nox;
    int oy  = t % OH;            t /= OH;
    int oc0 = (t % noc) * TOC;   int n = t / noc;
    long ex = n / wdiv;
    const float* wbase = fw + ex * PTOT + woff;
    const float* x     = in + (long)n * in_stride;

    float acc[TOC][TOX];
#pragma unroll
    for (int i = 0; i < TOC; i++) {
        float bv = fw[ex * PTOT + boff + oc0 + i];
#pragma unroll
        for (int j = 0; j < TOX; j++) acc[i][j] = bv;
    }
    int ixb = ox0 * S - 1;
    for (int ic = 0; ic < IC; ic++) {
        const float* xc = x + (long)ic * IH * IW;
#pragma unroll
        for (int ky = 0; ky < 3; ky++) {
            int iy = oy * S - 1 + ky;
            if ((unsigned)iy >= (unsigned)IH) continue;
            const float* xr = xc + iy * IW;
            float xv[XLEN];
#pragma unroll
            for (int u = 0; u < XLEN; u++) {
                int ix = ixb + u;
                xv[u] = ((unsigned)ix < (unsigned)IW) ? xr[ix] : 0.f;
            }
#pragma unroll
            for (int i = 0; i < TOC; i++) {
                const float* wp = wbase + ((long)(oc0 + i) * IC + ic) * 9 + ky * 3;
                float w0 = wp[0], w1 = wp[1], w2 = wp[2];
#pragma unroll
                for (int j = 0; j < TOX; j++)
                    acc[i][j] = fmaf(w0, xv[j * S],
                                fmaf(w1, xv[j * S + 1],
                                fmaf(w2, xv[j * S + 2], acc[i][j])));
            }
        }
    }
#pragma unroll
    for (int i = 0; i < TOC; i++) {
        float* op = out + (((long)n * OC + oc0 + i) * OH + oy) * OW + ox0;
#pragma unroll
        for (int j = 0; j < TOX; j++) op[j] = fmaxf(acc[i][j], 0.f);
    }
}

// IC-chunked conv fwd: atomic partial sums into zeroed out buffer.
template<int S, int TOC, int TOX>
__global__ void k_conv_fwd_chunk(const float* __restrict__ in, long in_stride,
                                 const float* __restrict__ fw, int woff, int wdiv,
                                 float* __restrict__ out,
                                 int N, int IC, int OC, int IH, int IW, int OH, int OW,
                                 int NCHUNK, int ICH)
{
    constexpr int XLEN = (TOX - 1) * S + 3;
    int nox = OW / TOX;
    int noc = OC / TOC;
    int base = N * noc * OH * nox;
    int idx = blockIdx.x * 256 + threadIdx.x;
    if (idx >= base * NCHUNK) return;
    int ch = idx / base; int r = idx % base;
    int ox0 = (r % nox) * TOX; int t = r / nox;
    int oy  = t % OH;          t /= OH;
    int oc0 = (t % noc) * TOC; int n = t / noc;
    long ex = n / wdiv;
    const float* wbase = fw + ex * PTOT + woff;
    const float* x     = in + (long)n * in_stride;

    float acc[TOC][TOX];
#pragma unroll
    for (int i = 0; i < TOC; i++)
#pragma unroll
        for (int j = 0; j < TOX; j++) acc[i][j] = 0.f;

    int ixb = ox0 * S - 1;
    int ic0 = ch * ICH;
    for (int ic = ic0; ic < ic0 + ICH; ic++) {
        const float* xc = x + (long)ic * IH * IW;
#pragma unroll
        for (int ky = 0; ky < 3; ky++) {
            int iy = oy * S - 1 + ky;
            if ((unsigned)iy >= (unsigned)IH) continue;
            const float* xr = xc + iy * IW;
            float xv[XLEN];
#pragma unroll
            for (int u = 0; u < XLEN; u++) {
                int ix = ixb + u;
                xv[u] = ((unsigned)ix < (unsigned)IW) ? xr[ix] : 0.f;
            }
#pragma unroll
            for (int i = 0; i < TOC; i++) {
                const float* wp = wbase + ((long)(oc0 + i) * IC + ic) * 9 + ky * 3;
                float w0 = wp[0], w1 = wp[1], w2 = wp[2];
#pragma unroll
                for (int j = 0; j < TOX; j++)
                    acc[i][j] = fmaf(w0, xv[j * S],
                                fmaf(w1, xv[j * S + 1],
                                fmaf(w2, xv[j * S + 2], acc[i][j])));
            }
        }
    }
#pragma unroll
    for (int i = 0; i < TOC; i++) {
        float* op = out + (((long)n * OC + oc0 + i) * OH + oy) * OW + ox0;
#pragma unroll
        for (int j = 0; j < TOX; j++) atomicAdd(op + j, acc[i][j]);
    }
}

// SMEM-staged conv fwd with fused bias+relu (test path, full IC in one kernel).
// Block = (n, OCB output channels). Stages ICH x IH x IW input chunk into padded smem.
// Threads: NPXG pixel-groups x NOCG oc-groups; thread's TOX pixels strided by NPXG.
template<int S, int ICH, int IH, int IW, int OH, int OW, int TOC, int TOX, int OCB>
__global__ void k_conv_smem(const float* __restrict__ in,
                            const float* __restrict__ fw, int woff, int boff, int wdiv,
                            float* __restrict__ out, int IC, int OC)
{
    constexpr int NPXG = (OH * OW) / TOX;
    constexpr int NOCG = OCB / TOC;
    constexpr int NTHR = NPXG * NOCG;
    constexpr int PADW = IW + 1;
    __shared__ float s_in[ICH * IH * PADW];

    int bi = blockIdx.x;
    int nblk = OC / OCB;
    int n   = bi / nblk;
    int ocb = (bi % nblk) * OCB;
    long ex = n / wdiv;
    const float* x  = in + (long)n * IC * IH * IW;
    const float* wb = fw + ex * PTOT + woff;

    int tid = threadIdx.x;
    int pxg = tid % NPXG;
    int ocg = tid / NPXG;
    int oc0 = ocb + ocg * TOC;

    int oyv[TOX], oxv[TOX];
#pragma unroll
    for (int j = 0; j < TOX; j++) {
        int p = pxg + NPXG * j;
        oyv[j] = p / OW;
        oxv[j] = p % OW;
    }

    float acc[TOC][TOX];
#pragma unroll
    for (int i = 0; i < TOC; i++)
#pragma unroll
        for (int j = 0; j < TOX; j++) acc[i][j] = 0.f;

    for (int c0 = 0; c0 < IC; c0 += ICH) {
        __syncthreads();
        for (int i = tid; i < ICH * IH * IW; i += NTHR) {
            int ic = i / (IH * IW); int r = i % (IH * IW);
            int iy = r / IW, ix = r % IW;
            s_in[(ic * IH + iy) * PADW + ix] = x[(long)(c0 + ic) * IH * IW + r];
        }
        __syncthreads();
        for (int ic = 0; ic < ICH; ic++) {
            const float* sc = s_in + ic * IH * PADW;
            const float* wic = wb + ((long)oc0 * IC + (c0 + ic)) * 9;
#pragma unroll
            for (int ky = 0; ky < 3; ky++) {
                float wr[TOC][3];
#pragma unroll
                for (int i = 0; i < TOC; i++) {
                    const float* wp = wic + (long)i * IC * 9 + ky * 3;
                    wr[i][0] = wp[0]; wr[i][1] = wp[1]; wr[i][2] = wp[2];
                }
#pragma unroll
                for (int j = 0; j < TOX; j++) {
                    int iy = oyv[j] * S + ky - 1;
                    if ((unsigned)iy >= (unsigned)IH) continue;
                    const float* srow = sc + iy * PADW;
                    int ixb = oxv[j] * S - 1;
                    float x0 = (ixb >= 0)       ? srow[ixb]     : 0.f;
                    float x1 =                    srow[ixb + 1];
                    float x2 = (ixb + 2 < IW)   ? srow[ixb + 2] : 0.f;
#pragma unroll
                    for (int i = 0; i < TOC; i++)
                        acc[i][j] = fmaf(wr[i][0], x0,
                                    fmaf(wr[i][1], x1,
                                    fmaf(wr[i][2], x2, acc[i][j])));
                }
            }
        }
    }
#pragma unroll
    for (int i = 0; i < TOC; i++) {
        float bv = fw[ex * PTOT + boff + oc0 + i];
#pragma unroll
        for (int j = 0; j < TOX; j++) {
            long o = (((long)n * OC + oc0 + i) * OH + oyv[j]) * OW + oxv[j];
            out[o] = fmaxf(acc[i][j] + bv, 0.f);
        }
    }
}

// in-place: out = relu(out + bias[oc])
__global__ void k_biasrelu(float* __restrict__ out, const float* __restrict__ fw,
                           int boff, int wdiv, int N, int OC, int OHW)
{
    int i = blockIdx.x * 256 + threadIdx.x;
    if (i >= N * OC * OHW) return;
    int oc = (i / OHW) % OC;
    long ex = (i / (OC * OHW)) / wdiv;
    out[i] = fmaxf(out[i] + fw[ex * PTOT + boff + oc], 0.f);
}

__global__ void k_gate(const float* __restrict__ a, const float* __restrict__ gate, int gstride,
                       float* __restrict__ o, int N)
{
    int i = blockIdx.x * 256 + threadIdx.x;
    if (i >= N * FEAT) return;
    int n = i / FEAT, m = i % FEAT;
    o[i] = a[i] * gate[(long)n * gstride + m];
}

__global__ void k_logit_init(const float* __restrict__ fw, int wdiv, float* __restrict__ logits, int N)
{
    int i = blockIdx.x * 256 + threadIdx.x;
    if (i >= N * NCLS) return;
    int cls = i % NCLS;
    long ex = (i / NCLS) / wdiv;
    logits[i] = fw[ex * PTOT + OFF_BO + cls];
}

__global__ void k_head_fwd_chunk(const float* __restrict__ feat, const float* __restrict__ fw,
                                 int wdiv, float* __restrict__ logits, int N)
{
    int gt = blockIdx.x * 256 + threadIdx.x;
    int warp = gt >> 5, lane = gt & 31;
    if (warp >= N * NCLS * 4) return;
    int ch = warp & 3; int w2 = warp >> 2;
    int cls = w2 % NCLS, n = w2 / NCLS;
    long ex = n / wdiv;
    const float* w = fw + ex * PTOT + OFF_WO + (long)cls * FEAT + ch * 1024;
    const float* f = feat + (long)n * FEAT + ch * 1024;
    float acc = 0.f;
#pragma unroll 8
    for (int m = lane; m < 1024; m += 32) acc = fmaf(w[m], f[m], acc);
#pragma unroll
    for (int o = 16; o; o >>= 1) acc += __shfl_down_sync(0xffffffffu, acc, o);
    if (!lane) atomicAdd(&logits[w2], acc);
}

__global__ void k_ce_grad(const float* __restrict__ logits, const int* __restrict__ y,
                          int ystride, int yoff, float* __restrict__ dlogit,
                          float* __restrict__ fw, const float* __restrict__ log_lr)
{
    int b = blockIdx.x, tid = threadIdx.x;
    __shared__ float red[128];
    float v = (tid < NCLS) ? logits[b * NCLS + tid] : -1e30f;
    red[tid] = v; __syncthreads();
    for (int s = 64; s > 0; s >>= 1) { if (tid < s) red[tid] = fmaxf(red[tid], red[tid + s]); __syncthreads(); }
    float m = red[0]; __syncthreads();
    float e = (tid < NCLS) ? expf(v - m) : 0.f;
    red[tid] = e; __syncthreads();
    for (int s = 64; s > 0; s >>= 1) { if (tid < s) red[tid] += red[tid + s]; __syncthreads(); }
    float sum = red[0];
    int label = y[b * ystride + yoff];
    if (tid < NCLS) {
        float dl = e / sum - (tid == label ? 1.f : 0.f);
        dlogit[b * NCLS + tid] = dl;
        fw[(long)b * PTOT + OFF_BO + tid] -= expf(*log_lr) * dl;
    }
}

__global__ void k_head_bwd_f_chunk(const float* __restrict__ dlogit, const float* __restrict__ fw,
                                   float* __restrict__ raw)
{
    int i = blockIdx.x * 256 + threadIdx.x;
    if (i >= NB * 4 * FEAT) return;
    int m = i % FEAT; int t = i / FEAT;
    int ch = t % 4; int b = t / 4;
    const float* w  = fw + (long)b * PTOT + OFF_WO + m + (long)(ch * 25) * FEAT;
    const float* dl = dlogit + b * NCLS + ch * 25;
    float acc = 0.f;
#pragma unroll
    for (int n = 0; n < 25; n++) acc = fmaf(w[(long)n * FEAT], dl[n], acc);
    atomicAdd(&raw[(long)b * FEAT + m], acc);
}

__global__ void k_mask_gate(const float* __restrict__ raw, const float* __restrict__ a5,
                            const float* __restrict__ gate, int gstride, float* __restrict__ dz)
{
    int i = blockIdx.x * 256 + threadIdx.x;
    if (i >= NB * FEAT) return;
    int m = i % FEAT, b = i / FEAT;
    dz[i] = (a5[i] > 0.f) ? raw[i] * gate[(long)b * gstride + m] : 0.f;
}

__global__ void k_head_upd_w(const float* __restrict__ dlogit, const float* __restrict__ feat,
                             float* __restrict__ fw, const float* __restrict__ log_lr)
{
    int i = blockIdx.x * 256 + threadIdx.x;
    if (i >= NB * NCLS * FEAT) return;
    int m = i % FEAT; int t = i / FEAT;
    int cls = t % NCLS; int b = t / NCLS;
    fw[(long)b * PTOT + OFF_WO + (long)cls * FEAT + m] -=
        expf(*log_lr) * dlogit[b * NCLS + cls] * feat[(long)b * FEAT + m];
}

__global__ void k_bwd_b_upd(const float* __restrict__ dz, float* __restrict__ fw,
                            const float* __restrict__ log_lr, int boff, int OC, int OHW)
{
    int gt = blockIdx.x * 256 + threadIdx.x;
    int warp = gt >> 5, lane = gt & 31;
    if (warp >= NB * OC) return;
    int oc = warp % OC, b = warp / OC;
    const float* p = dz + ((long)b * OC + oc) * OHW;
    float acc = 0.f;
    for (int i = lane; i < OHW; i += 32) acc += p[i];
#pragma unroll
    for (int o = 16; o; o >>= 1) acc += __shfl_down_sync(0xffffffffu, acc, o);
    if (!lane) fw[(long)b * PTOT + boff + oc] -= expf(*log_lr) * acc;
}

// WARP-COOPERATIVE weight grad + fused SGD.
template<int S>
__global__ void k_bwd_w_warp(const float* __restrict__ dz, const float* __restrict__ xin, long xstride,
                             float* __restrict__ fw, const float* __restrict__ log_lr, int woff,
                             int IC, int OC, int IH, int IW, int OH, int OW, int NCH)
{
    long gt = blockIdx.x * 256L + threadIdx.x;
    long w = gt >> 5; int lane = (int)(gt & 31);
    if (w >= (long)NB * OC * IC * NCH) return;
    int c  = (int)(w % NCH); long t = w / NCH;
    int ic = (int)(t % IC); t /= IC;
    int oc = (int)(t % OC); int b = (int)(t / OC);
    int CH = OH / NCH;
    const float* x = xin + (long)b * xstride + (long)ic * IH * IW;
    const float* z = dz + ((long)b * OC + oc) * OH * OW;
    float acc[9];
#pragma unroll
    for (int k = 0; k < 9; k++) acc[k] = 0.f;
    int oybase = c * CH;
    int npix = CH * OW;
    for (int p = lane; p < npix; p += 32) {
        int oy = oybase + p / OW;
        int ox = p % OW;
        float zv = z[oy * OW + ox];
#pragma unroll
        for (int ky = 0; ky < 3; ky++) {
            int iy = oy * S + ky - 1;
            if ((unsigned)iy >= (unsigned)IH) continue;
            const float* xr = x + iy * IW;
            int ixb = ox * S - 1;
#pragma unroll
            for (int kx = 0; kx < 3; kx++) {
                int ix = ixb + kx;
                if ((unsigned)ix < (unsigned)IW)
                    acc[ky * 3 + kx] = fmaf(zv, xr[ix], acc[ky * 3 + kx]);
            }
        }
    }
    float nlr = -expf(*log_lr);
    float* g = fw + (long)b * PTOT + woff + ((long)oc * IC + ic) * 9;
#pragma unroll
    for (int k = 0; k < 9; k++) {
        float v = acc[k];
#pragma unroll
        for (int o = 16; o; o >>= 1) v += __shfl_down_sync(0xffffffffu, v, o);
        if (!lane) atomicAdd(g + k, nlr * v);
    }
}

// OC-chunked bwd_x (stride-2): atomicAdd raw dx for 4 consecutive pixels.
__global__ void k_bwd_x_chunk(const float* __restrict__ dz, const float* __restrict__ fw, int woff,
                              float* __restrict__ raw,
                              int IC, int OC, int IH, int IW, int OH, int OW,
                              int NCHUNK, int OCH)
{
    int nix = IW >> 2;
    int base = NB * IC * IH * nix;
    int idx = blockIdx.x * 256 + threadIdx.x;
    if (idx >= base * NCHUNK) return;
    int ch = idx / base; int r = idx % base;
    int ix0 = (r % nix) * 4; int t = r / nix;
    int iy = t % IH; t /= IH;
    int ic = t % IC; int b = t / IC;
    long pix = (((long)b * IC + ic) * IH + iy) * IW + ix0;

    float acc0 = 0.f, acc1 = 0.f, acc2 = 0.f, acc3 = 0.f;
    int ox0p = ix0 >> 1;
    bool ok2 = (ox0p + 2 < OW), ok1 = (ox0p + 1 < OW);

    int oyv[3]; bool kyok[3];
#pragma unroll
    for (int ky = 0; ky < 3; ky++) {
        int ty = iy + 1 - ky;
        kyok[ky] = (ty >= 0) && !(ty & 1) && ((ty >> 1) < OH);
        oyv[ky] = ty >> 1;
    }
    const float* wb = fw + (long)b * PTOT + woff + (long)ic * 9;
    const float* zb = dz + (long)b * OC * OH * OW;
    int oc0 = ch * OCH;
    for (int oc = oc0; oc < oc0 + OCH; oc++) {
        const float* wp = wb + (long)oc * IC * 9;
        const float* zp = zb + (long)oc * OH * OW;
#pragma unroll
        for (int ky = 0; ky < 3; ky++) {
            if (!kyok[ky]) continue;
            const float* zr = zp + oyv[ky] * OW;
            float d0 = zr[ox0p];
            float d1 = ok1 ? zr[ox0p + 1] : 0.f;
            float d2 = ok2 ? zr[ox0p + 2] : 0.f;
            float wk0 = wp[ky * 3 + 0], wk1 = wp[ky * 3 + 1], wk2 = wp[ky * 3 + 2];
            acc0 = fmaf(wk1, d0, acc0);
            acc1 = fmaf(wk0, d1, fmaf(wk2, d0, acc1));
            acc2 = fmaf(wk1, d1, acc2);
            acc3 = fmaf(wk0, d2, fmaf(wk2, d1, acc3));
        }
    }
    atomicAdd(&raw[pix],     acc0);
    atomicAdd(&raw[pix + 1], acc1);
    atomicAdd(&raw[pix + 2], acc2);
    atomicAdd(&raw[pix + 3], acc3);
}

__global__ void k_mask(const float* __restrict__ raw, const float* __restrict__ act,
                       float* __restrict__ dz, int count)
{
    int i = blockIdx.x * 256 + threadIdx.x;
    if (i < count) dz[i] = (act[i] > 0.f) ? raw[i] : 0.f;
}

__global__ void k_loss_eval(const float* __restrict__ logits, const int* __restrict__ y,
                            const float* __restrict__ log_lr, float* __restrict__ out)
{
    int e = blockIdx.x, tid = threadIdx.x;
    __shared__ float rv[128];
    __shared__ int   ri[128];
    float v = (tid < NCLS) ? logits[e * NCLS + tid] : -1e30f;
    rv[tid] = v; ri[tid] = tid; __syncthreads();
    for (int s = 64; s > 0; s >>= 1) {
        if (tid < s) {
            if (rv[tid + s] > rv[tid] || (rv[tid + s] == rv[tid] && ri[tid + s] < ri[tid])) {
                rv[tid] = rv[tid + s]; ri[tid] = ri[tid + s];
            }
        }
        __syncthreads();
    }
    float m = rv[0]; int amax = ri[0]; __syncthreads();
    float ex = (tid < NCLS) ? expf(v - m) : 0.f;
    rv[tid] = ex; __syncthreads();
    for (int s = 64; s > 0; s >>= 1) { if (tid < s) rv[tid] += rv[tid + s]; __syncthreads(); }
    if (tid == 0) {
        float lse = m + logf(rv[0]);
        int label = y[e];
        out[e]        = lse - logits[e * NCLS + label];
        out[129 + e]  = (amax == label) ? 1.f : 0.f;
        if (e == 0) out[128] = expf(*log_lr);
    }
}

// ---------------- launcher ----------------
struct LC { int ic, oc, ih, iw, oh, ow, s; };
static const LC lc[5] = {
    {  3,  32, 64, 64, 64, 64, 1},
    { 32,  64, 64, 64, 32, 32, 2},
    { 64, 128, 32, 32, 16, 16, 2},
    {128, 256, 16, 16,  8,  8, 2},
    {256, 256,  8,  8,  4,  4, 2},
};
static const int woffs[5] = {OFF_W0, OFF_W1, OFF_W2, OFF_W3, OFF_W4};
static const int boffs[5] = {OFF_B0, OFF_B1, OFF_B2, OFF_B3, OFF_B4};

static inline unsigned GRID(long n) { return (unsigned)((n + 255) / 256); }

extern "C" void kernel_launch(void* const* d_in, const int* in_sizes, int n_in,
                              void* d_out, int out_size)
{
    const float* pw[12];
    for (int i = 0; i < 12; i++) pw[i] = (const float*)d_in[i];
    const float* log_lr     = (const float*)d_in[12];
    const float* train_x    = (const float*)d_in[13];
    const float* test_x     = (const float*)d_in[14];
    const float* train_gate = (const float*)d_in[15];
    const float* test_gate  = (const float*)d_in[16];
    const int*   train_y    = (const int*)d_in[17];
    const int*   test_y     = (const int*)d_in[18];
    float* out = (float*)d_out;

    float *fw, *a1, *a2, *a3, *a4, *a5, *feat, *logit, *dlogit, *d1, *d2, *ta, *tb;
    cudaGetSymbolAddress((void**)&fw,     g_fw);
    cudaGetSymbolAddress((void**)&a1,     g_a1);
    cudaGetSymbolAddress((void**)&a2,     g_a2);
    cudaGetSymbolAddress((void**)&a3,     g_a3);
    cudaGetSymbolAddress((void**)&a4,     g_a4);
    cudaGetSymbolAddress((void**)&a5,     g_a5);
    cudaGetSymbolAddress((void**)&feat,   g_feat);
    cudaGetSymbolAddress((void**)&logit,  g_logit);
    cudaGetSymbolAddress((void**)&dlogit, g_dlogit);
    cudaGetSymbolAddress((void**)&d1,     g_d1);
    cudaGetSymbolAddress((void**)&d2,     g_d2);
    cudaGetSymbolAddress((void**)&ta,     g_ta);
    cudaGetSymbolAddress((void**)&tb,     g_tb);

    float* acts[6] = {nullptr, a1, a2, a3, a4, a5};

    const int f_ich[5] = {0, 8, 8, 8, 4};
    const int wnch[5] = {16, 4, 2, 1, 1};

    k_bcast_all<<<GRID((long)NB * PTOT), 256>>>(pw[0], pw[1], pw[2], pw[3], pw[4], pw[5],
                                                pw[6], pw[7], pw[8], pw[9], pw[10], pw[11], fw);

    auto fwd_inner_conv = [&](int j, const float* in, float* o) {
        const LC& L = lc[j];
        int ich = f_ich[j], nch = L.ic / ich;
        long instr = (long)L.ic * L.ih * L.iw;
        long tot = (long)NB * (L.oc / 4) * L.oh * (L.ow / 4) * nch;
        k_conv_fwd_chunk<2, 4, 4><<<GRID(tot), 256>>>(in, instr, fw, woffs[j], 1, o,
            NB, L.ic, L.oc, L.ih, L.iw, L.oh, L.ow, nch, ich);
        long osz = (long)NB * L.oc * L.oh * L.ow;
        k_biasrelu<<<GRID(osz), 256>>>(o, fw, boffs[j], 1, NB, L.oc, L.oh * L.ow);
    };
    auto bwd_w = [&](int j, const float* dzb, const float* xin, long xstride) {
        const LC& L = lc[j];
        long warps = (long)NB * L.oc * L.ic * wnch[j];
        if (L.s == 2)
            k_bwd_w_warp<2><<<GRID(warps * 32), 256>>>(dzb, xin, xstride, fw, log_lr, woffs[j],
                L.ic, L.oc, L.ih, L.iw, L.oh, L.ow, wnch[j]);
        else
            k_bwd_w_warp<1><<<GRID(warps * 32), 256>>>(dzb, xin, xstride, fw, log_lr, woffs[j],
                L.ic, L.oc, L.ih, L.iw, L.oh, L.ow, wnch[j]);
    };

    // -------- inner loop (unchanged from R9) --------
    for (int t = 0; t < NT; t++) {
        const float* in0 = train_x + (long)t * CHW;
        {
            long tot = (long)NB * (32 / 4) * 64 * (64 / 4);
            k_conv_fwd_t<1, 4, 4><<<GRID(tot), 256>>>(in0, (long)NT * CHW, fw, OFF_W0, OFF_B0, 1, a1,
                                                      NB, 3, 32, 64, 64, 64, 64);
        }
        cudaMemsetAsync(a2, 0, (long)NB * 65536 * sizeof(float));
        cudaMemsetAsync(a3, 0, (long)NB * 32768 * sizeof(float));
        cudaMemsetAsync(a4, 0, (long)NB * 16384 * sizeof(float));
        cudaMemsetAsync(a5, 0, (long)NB * 4096 * sizeof(float));
        fwd_inner_conv(1, a1, a2);
        fwd_inner_conv(2, a2, a3);
        fwd_inner_conv(3, a3, a4);
        fwd_inner_conv(4, a4, a5);
        k_gate<<<GRID((long)NB * FEAT), 256>>>(a5, train_gate + (long)t * FEAT, NT * FEAT, feat, NB);
        k_logit_init<<<GRID((long)NB * NCLS), 256>>>(fw, 1, logit, NB);
        k_head_fwd_chunk<<<GRID((long)NB * NCLS * 4 * 32), 256>>>(feat, fw, 1, logit, NB);
        k_ce_grad<<<NB, 128>>>(logit, train_y, NT, t, dlogit, fw, log_lr);
        cudaMemsetAsync(d2, 0, (long)NB * FEAT * sizeof(float));
        k_head_bwd_f_chunk<<<GRID((long)NB * 4 * FEAT), 256>>>(dlogit, fw, d2);
        k_mask_gate<<<GRID((long)NB * FEAT), 256>>>(d2, a5, train_gate + (long)t * FEAT, NT * FEAT, d1);
        k_head_upd_w<<<GRID((long)NB * NCLS * FEAT), 256>>>(dlogit, feat, fw, log_lr);

        for (int j = 4; j >= 1; j--) {
            const LC& L = lc[j];
            long insz = (long)NB * L.ic * L.ih * L.iw;
            long instr = (long)L.ic * L.ih * L.iw;
            k_bwd_b_upd<<<GRID((long)NB * L.oc * 32), 256>>>(d1, fw, log_lr, boffs[j],
                                                             L.oc, L.oh * L.ow);
            cudaMemsetAsync(d2, 0, insz * sizeof(float));
            {
                int nch = L.oc / 8;
                long tot = (long)NB * L.ic * L.ih * (L.iw / 4) * nch;
                k_bwd_x_chunk<<<GRID(tot), 256>>>(d1, fw, woffs[j], d2,
                    L.ic, L.oc, L.ih, L.iw, L.oh, L.ow, nch, 8);
            }
            bwd_w(j, d1, acts[j], instr);
            k_mask<<<GRID(insz), 256>>>(d2, acts[j], d1, (int)insz);
        }
        k_bwd_b_upd<<<GRID((long)NB * 32 * 32), 256>>>(d1, fw, log_lr, OFF_B0, 32, 64 * 64);
        bwd_w(0, d1, in0, (long)NT * CHW);
    }

    // -------- test forward --------
    // L0: direct (IC=3)
    {
        long tot = (long)NTEST * (32 / 4) * 64 * (64 / 4);
        k_conv_fwd_t<1, 4, 4><<<GRID(tot), 256>>>(test_x, (long)CHW, fw, OFF_W0, OFF_B0, NL, ta,
                                                  NTEST, 3, 32, 64, 64, 64, 64);
    }
    // L1: smem conv  (S=2, ICH=4, IH=IW=64, OH=OW=32, TOC=8, TOX=4, OCB=8) -> NPXG=256, NOCG=1
    k_conv_smem<2, 4, 64, 64, 32, 32, 8, 4, 8><<<NTEST * (64 / 8), 256>>>(
        ta, fw, OFF_W1, OFF_B1, NL, tb, 32, 64);
    // L2: smem conv  (S=2, ICH=8, IH=IW=32, OH=OW=16, TOC=8, TOX=4, OCB=32) -> NPXG=64, NOCG=4
    k_conv_smem<2, 8, 32, 32, 16, 16, 8, 4, 32><<<NTEST * (128 / 32), 256>>>(
        tb, fw, OFF_W2, OFF_B2, NL, ta, 64, 128);
    // L3: smem conv  (S=2, ICH=32, IH=IW=16, OH=OW=8, TOC=8, TOX=4, OCB=128) -> NPXG=16, NOCG=16
    k_conv_smem<2, 32, 16, 16, 8, 8, 8, 4, 128><<<NTEST * (256 / 128), 256>>>(
        ta, fw, OFF_W3, OFF_B3, NL, tb, 128, 256);
    // L4: keep chunked path (weight-traffic dominated; smem doesn't help at 16 px)
    {
        const LC& L = lc[4];
        long osz = (long)NTEST * L.oc * L.oh * L.ow;
        cudaMemsetAsync(ta, 0, osz * sizeof(float));
        int ich = 32, nch = L.ic / ich;
        long instr = (long)L.ic * L.ih * L.iw;
        long tot = (long)NTEST * (L.oc / 8) * L.oh * (L.ow / 4) * nch;
        k_conv_fwd_chunk<2, 8, 4><<<GRID(tot), 256>>>(tb, instr, fw, woffs[4], NL, ta,
            NTEST, L.ic, L.oc, L.ih, L.iw, L.oh, L.ow, nch, ich);
        k_biasrelu<<<GRID(osz), 256>>>(ta, fw, boffs[4], NL, NTEST, L.oc, L.oh * L.ow);
    }
    k_gate<<<GRID((long)NTEST * FEAT), 256>>>(ta, test_gate, FEAT, tb, NTEST);
    k_logit_init<<<GRID((long)NTEST * NCLS), 256>>>(fw, NL, out + 257, NTEST);
    k_head_fwd_chunk<<<GRID((long)NTEST * NCLS * 4 * 32), 256>>>(tb, fw, NL, out + 257, NTEST);
    k_loss_eval<<<NTEST, 128>>>(out + 257, test_y, log_lr, out);
}